// round 1
// baseline (speedup 1.0000x reference)
#include <cuda_runtime.h>
#include <math.h>
#include <stdint.h>

#define NN   50000
#define EE   800000
#define MM   3
#define INSZ 256
#define HDIM 128      // HEADS*HID
#define NH   8
#define DH   16
#define OUTC 8
#define SAH  128
#define ZROW (MM*HDIM)  // 384

// ---------------- scratch (device globals; no allocation) ----------------
__device__ float g_feat[(size_t)MM*NN*HDIM];   // [m][n][128]
__device__ float g_z[(size_t)NN*MM*HDIM];      // [n][m][128]
__device__ float g_el[MM*NN*NH];
__device__ float g_er[MM*NN*NH];
__device__ int   g_deg[MM*NN];
__device__ int   g_off[MM*(NN+1)];
__device__ int   g_cur[MM*NN];
__device__ int   g_srt[MM*EE];
__device__ float g_w[NN*MM];                   // row = n*3+m
__device__ float g_s[NN*MM];
__device__ float g_wmax[MM];
__device__ float g_den[MM];
__device__ float g_fus[MM*HDIM];

__device__ __forceinline__ void atomicMaxF(float* addr, float v) {
    if (v >= 0.f) atomicMax((int*)addr, __float_as_int(v));
    else          atomicMin((unsigned int*)addr, __float_as_uint(v));
}

// ---------------- init scratch each replay ----------------
__global__ void k_init() {
    int idx = blockIdx.x * blockDim.x + threadIdx.x;
    if (idx < MM*NN) g_deg[idx] = 0;
    if (idx < MM*HDIM) g_fus[idx] = 0.f;
    if (idx < MM) { g_den[idx] = 0.f; g_wmax[idx] = -INFINITY; }
}

// ---------------- feat = h @ fc_w[m]  (tiled fp32 GEMM) ----------------
// BM=64, BN=128 (full), BK=16, 256 threads, 8x4 micro-tile.
__global__ __launch_bounds__(256) void k_gemm_feat(const float* __restrict__ A,
                                                   const float* __restrict__ W) {
    __shared__ float As[64][16];
    __shared__ float Bs[16][128];
    int m    = blockIdx.z;
    int row0 = blockIdx.y * 64;
    int tid  = threadIdx.x;
    int tx   = tid & 31;      // col group: cols tx*4..tx*4+3
    int ty   = tid >> 5;      // row group: rows ty*8..ty*8+7
    const float* Wm = W + (size_t)m * INSZ * HDIM;

    float acc[8][4];
#pragma unroll
    for (int i = 0; i < 8; i++)
#pragma unroll
        for (int j = 0; j < 4; j++) acc[i][j] = 0.f;

    for (int k0 = 0; k0 < INSZ; k0 += 16) {
        {   // A tile: 64x16, one float4 per thread
            int r = tid >> 2, c = tid & 3;
            float4 v = make_float4(0.f, 0.f, 0.f, 0.f);
            int row = row0 + r;
            if (row < NN) v = *(const float4*)(A + (size_t)row * INSZ + k0 + c * 4);
            *(float4*)&As[r][c * 4] = v;
        }
#pragma unroll
        for (int j = 0; j < 2; j++) { // B tile: 16x128, two float4 per thread
            int idx = tid + j * 256;
            int r = idx >> 5, c = idx & 31;
            *(float4*)&Bs[r][c * 4] = *(const float4*)(Wm + (size_t)(k0 + r) * HDIM + c * 4);
        }
        __syncthreads();
#pragma unroll
        for (int kk = 0; kk < 16; kk++) {
            float4 b = *(float4*)&Bs[kk][tx * 4];
#pragma unroll
            for (int i = 0; i < 8; i++) {
                float a = As[ty * 8 + i][kk];
                acc[i][0] += a * b.x; acc[i][1] += a * b.y;
                acc[i][2] += a * b.z; acc[i][3] += a * b.w;
            }
        }
        __syncthreads();
    }
    float* outp = g_feat + (size_t)m * NN * HDIM;
#pragma unroll
    for (int i = 0; i < 8; i++) {
        int row = row0 + ty * 8 + i;
        if (row < NN) {
            float4 v = make_float4(acc[i][0], acc[i][1], acc[i][2], acc[i][3]);
            *(float4*)(outp + (size_t)row * HDIM + tx * 4) = v;
        }
    }
}

// ---------------- el/er per (m,n,h) ----------------
__global__ void k_eler(const float* __restrict__ al, const float* __restrict__ ar) {
    int idx = blockIdx.x * blockDim.x + threadIdx.x;
    if (idx >= MM * NN * NH) return;
    int m = idx / (NN * NH);
    int r = idx - m * NN * NH;
    int n = r / NH, h = r - n * NH;
    const float* f  = g_feat + (size_t)m * NN * HDIM + (size_t)n * HDIM + h * DH;
    const float* a1 = al + (m * NH + h) * DH;
    const float* a2 = ar + (m * NH + h) * DH;
    float sl = 0.f, sr = 0.f;
#pragma unroll
    for (int d = 0; d < DH; d++) {
        float fv = f[d];
        sl += fv * __ldg(a1 + d);
        sr += fv * __ldg(a2 + d);
    }
    g_el[idx] = sl;
    g_er[idx] = sr;
}

// ---------------- CSR build ----------------
__global__ void k_hist(const int* __restrict__ edges) {
    int idx = blockIdx.x * blockDim.x + threadIdx.x;
    if (idx >= MM * EE) return;
    int m = idx / EE, e = idx - m * EE;
    int dst = edges[(size_t)m * 2 * EE + EE + e];
    atomicAdd(&g_deg[m * NN + dst], 1);
}

__global__ void k_scan() {
    __shared__ int sh[1024];
    int m = blockIdx.x;
    int t = threadIdx.x;
    const int CH = (NN + 1023) / 1024; // 49
    int base = t * CH;
    int sum = 0;
    for (int i = 0; i < CH; i++) {
        int idx = base + i;
        if (idx < NN) sum += g_deg[m * NN + idx];
    }
    sh[t] = sum;
    __syncthreads();
    for (int d = 1; d < 1024; d <<= 1) {
        int v = (t >= d) ? sh[t - d] : 0;
        __syncthreads();
        sh[t] += v;
        __syncthreads();
    }
    int run = sh[t] - sum; // exclusive prefix
    for (int i = 0; i < CH; i++) {
        int idx = base + i;
        if (idx < NN) {
            g_off[m * (NN + 1) + idx] = run;
            g_cur[m * NN + idx] = run;
            run += g_deg[m * NN + idx];
        }
    }
    if (t == 1023) g_off[m * (NN + 1) + NN] = sh[1023];
}

__global__ void k_scatter(const int* __restrict__ edges) {
    int idx = blockIdx.x * blockDim.x + threadIdx.x;
    if (idx >= MM * EE) return;
    int m = idx / EE, e = idx - m * EE;
    int src = edges[(size_t)m * 2 * EE + e];
    int dst = edges[(size_t)m * 2 * EE + EE + e];
    int p = atomicAdd(&g_cur[m * NN + dst], 1);
    g_srt[(size_t)m * EE + p] = src;
}

// ---------------- GAT aggregation: warp per dst node, online softmax ----------------
__global__ __launch_bounds__(256) void k_agg() {
    int lane = threadIdx.x & 31;
    int wid  = (blockIdx.x * blockDim.x + threadIdx.x) >> 5;
    int m    = blockIdx.y;
    if (wid >= NN) return;
    int n = wid;
    int h = lane >> 2;                 // head for this lane's 4 dims
    int beg = g_off[m * (NN + 1) + n];
    int end = g_off[m * (NN + 1) + n + 1];
    float ern = g_er[(m * NN + n) * NH + h];
    const float* featm = g_feat + (size_t)m * NN * HDIM;
    const float* elm   = g_el + m * NN * NH;
    const int*   srcs  = g_srt + (size_t)m * EE;

    float mx = -INFINITY, den = 0.f;
    float ax = 0.f, ay = 0.f, az = 0.f, aw = 0.f;
    for (int i = beg; i < end; i++) {
        int s = srcs[i];
        float e = elm[s * NH + h] + ern;
        e = (e > 0.f) ? e : 0.2f * e;          // leaky_relu
        float nm = fmaxf(mx, e);
        float sc = __expf(mx - nm);            // first iter: exp(-inf)=0
        float ex = __expf(e - nm);
        mx = nm;
        den = den * sc + ex;
        float4 f = *(const float4*)(featm + (size_t)s * HDIM + lane * 4);
        ax = ax * sc + ex * f.x;
        ay = ay * sc + ex * f.y;
        az = az * sc + ex * f.z;
        aw = aw * sc + ex * f.w;
    }
    float inv = (end > beg) ? 1.f / den : 0.f;
    float4 o;
    float v;
    v = ax * inv; o.x = (v > 0.f) ? v : expm1f(v);
    v = ay * inv; o.y = (v > 0.f) ? v : expm1f(v);
    v = az * inv; o.z = (v > 0.f) ? v : expm1f(v);
    v = aw * inv; o.w = (v > 0.f) ? v : expm1f(v);
    *(float4*)(g_z + (size_t)(n * MM + m) * HDIM + lane * 4) = o;
}

// ---------------- SA: w = tanh(z @ sa_w1 + b1) @ sa_w2, fused GEMM ----------------
__global__ __launch_bounds__(256) void k_sa(const float* __restrict__ W1,
                                            const float* __restrict__ B1,
                                            const float* __restrict__ W2) {
    __shared__ float As[64][16];
    __shared__ float Bs[16][128];
    const int ROWS = NN * MM;
    int row0 = blockIdx.y * 64;
    int tid  = threadIdx.x;
    int tx   = tid & 31, ty = tid >> 5;

    float acc[8][4];
#pragma unroll
    for (int i = 0; i < 8; i++)
#pragma unroll
        for (int j = 0; j < 4; j++) acc[i][j] = 0.f;

    for (int k0 = 0; k0 < HDIM; k0 += 16) {
        {
            int r = tid >> 2, c = tid & 3;
            float4 v = make_float4(0.f, 0.f, 0.f, 0.f);
            int row = row0 + r;
            if (row < ROWS) v = *(const float4*)(g_z + (size_t)row * HDIM + k0 + c * 4);
            *(float4*)&As[r][c * 4] = v;
        }
#pragma unroll
        for (int j = 0; j < 2; j++) {
            int idx = tid + j * 256;
            int r = idx >> 5, c = idx & 31;
            *(float4*)&Bs[r][c * 4] = *(const float4*)(W1 + (size_t)(k0 + r) * SAH + c * 4);
        }
        __syncthreads();
#pragma unroll
        for (int kk = 0; kk < 16; kk++) {
            float4 b = *(float4*)&Bs[kk][tx * 4];
#pragma unroll
            for (int i = 0; i < 8; i++) {
                float a = As[ty * 8 + i][kk];
                acc[i][0] += a * b.x; acc[i][1] += a * b.y;
                acc[i][2] += a * b.z; acc[i][3] += a * b.w;
            }
        }
        __syncthreads();
    }
    float4 b1 = *(const float4*)(B1 + tx * 4);
    float4 w2 = *(const float4*)(W2 + tx * 4);
#pragma unroll
    for (int i = 0; i < 8; i++) {
        float p = tanhf(acc[i][0] + b1.x) * w2.x
                + tanhf(acc[i][1] + b1.y) * w2.y
                + tanhf(acc[i][2] + b1.z) * w2.z
                + tanhf(acc[i][3] + b1.w) * w2.w;
#pragma unroll
        for (int off = 16; off > 0; off >>= 1)
            p += __shfl_down_sync(0xffffffffu, p, off);
        if (tx == 0) {
            int row = row0 + ty * 8 + i;
            if (row < ROWS) g_w[row] = p;
        }
    }
}

// ---------------- softmax over nodes ----------------
__global__ void k_wmax() {
    float lm0 = -INFINITY, lm1 = -INFINITY, lm2 = -INFINITY;
    for (int n = blockIdx.x * blockDim.x + threadIdx.x; n < NN; n += gridDim.x * blockDim.x) {
        lm0 = fmaxf(lm0, g_w[n * 3 + 0]);
        lm1 = fmaxf(lm1, g_w[n * 3 + 1]);
        lm2 = fmaxf(lm2, g_w[n * 3 + 2]);
    }
#pragma unroll
    for (int off = 16; off > 0; off >>= 1) {
        lm0 = fmaxf(lm0, __shfl_down_sync(0xffffffffu, lm0, off));
        lm1 = fmaxf(lm1, __shfl_down_sync(0xffffffffu, lm1, off));
        lm2 = fmaxf(lm2, __shfl_down_sync(0xffffffffu, lm2, off));
    }
    if ((threadIdx.x & 31) == 0) {
        atomicMaxF(&g_wmax[0], lm0);
        atomicMaxF(&g_wmax[1], lm1);
        atomicMaxF(&g_wmax[2], lm2);
    }
}

__global__ void k_sden() {
    float w0 = g_wmax[0], w1 = g_wmax[1], w2 = g_wmax[2];
    float d0 = 0.f, d1 = 0.f, d2 = 0.f;
    for (int n = blockIdx.x * blockDim.x + threadIdx.x; n < NN; n += gridDim.x * blockDim.x) {
        float s0 = __expf(g_w[n * 3 + 0] - w0);
        float s1 = __expf(g_w[n * 3 + 1] - w1);
        float s2 = __expf(g_w[n * 3 + 2] - w2);
        g_s[n * 3 + 0] = s0; g_s[n * 3 + 1] = s1; g_s[n * 3 + 2] = s2;
        d0 += s0; d1 += s1; d2 += s2;
    }
#pragma unroll
    for (int off = 16; off > 0; off >>= 1) {
        d0 += __shfl_down_sync(0xffffffffu, d0, off);
        d1 += __shfl_down_sync(0xffffffffu, d1, off);
        d2 += __shfl_down_sync(0xffffffffu, d2, off);
    }
    if ((threadIdx.x & 31) == 0) {
        atomicAdd(&g_den[0], d0);
        atomicAdd(&g_den[1], d1);
        atomicAdd(&g_den[2], d2);
    }
}

// fused[m][c] = sum_n s[n][m] * z[n][m][c]   (384 threads own one (m,c) each)
__global__ __launch_bounds__(384) void k_fused() {
    int t = threadIdx.x;            // t = m*128 + c
    int ms = t >> 7;                // m
    float acc = 0.f;
    for (int n = blockIdx.x; n < NN; n += gridDim.x) {
        float s = g_s[n * 3 + ms];
        acc += s * g_z[(size_t)n * ZROW + t];
    }
    atomicAdd(&g_fus[t], acc);
}

__global__ void k_final(const float* __restrict__ PW, const float* __restrict__ PB,
                        float* __restrict__ out) {
    int t = threadIdx.x;
    if (t >= MM * OUTC) return;
    int m = t / OUTC, o = t - m * OUTC;
    float a = 0.f;
#pragma unroll 8
    for (int c = 0; c < HDIM; c++)
        a += g_fus[m * HDIM + c] * __ldg(PW + c * OUTC + o);
    out[t] = a / g_den[m] + __ldg(PB + o);
}

// ---------------- launcher ----------------
extern "C" void kernel_launch(void* const* d_in, const int* in_sizes, int n_in,
                              void* d_out, int out_size) {
    const float* h      = (const float*)d_in[0];
    const int*   edges  = (const int*)d_in[1];
    const float* fc_w   = (const float*)d_in[2];
    const float* attn_l = (const float*)d_in[3];
    const float* attn_r = (const float*)d_in[4];
    const float* sa_w1  = (const float*)d_in[5];
    const float* sa_b1  = (const float*)d_in[6];
    const float* sa_w2  = (const float*)d_in[7];
    const float* pred_w = (const float*)d_in[8];
    const float* pred_b = (const float*)d_in[9];
    float* out = (float*)d_out;

    k_init<<<(MM * NN + 255) / 256, 256>>>();
    k_gemm_feat<<<dim3(1, (NN + 63) / 64, MM), 256>>>(h, fc_w);
    k_eler<<<(MM * NN * NH + 255) / 256, 256>>>(attn_l, attn_r);
    k_hist<<<(MM * EE + 255) / 256, 256>>>(edges);
    k_scan<<<MM, 1024>>>();
    k_scatter<<<(MM * EE + 255) / 256, 256>>>(edges);
    k_agg<<<dim3((NN + 7) / 8, MM), 256>>>();
    k_sa<<<dim3(1, (NN * MM + 63) / 64), 256>>>(sa_w1, sa_b1, sa_w2);
    k_wmax<<<64, 256>>>();
    k_sden<<<196, 256>>>();
    k_fused<<<256, 384>>>();
    k_final<<<1, 32>>>(pred_w, pred_b, out);
}

// round 2
// speedup vs baseline: 1.0090x; 1.0090x over previous
#include <cuda_runtime.h>
#include <math.h>
#include <stdint.h>

#define NN   50000
#define EE   800000
#define MM   3
#define INSZ 256
#define HDIM 128      // HEADS*HID
#define NH   8
#define DH   16
#define OUTC 8
#define SAH  128
#define ZROW (MM*HDIM)  // 384

// ---------------- scratch (device globals; no allocation) ----------------
__device__ float g_feat[(size_t)MM*NN*HDIM];   // [m][n][128]
__device__ float g_z[(size_t)NN*MM*HDIM];      // [n][m][128]
__device__ float g_el[MM*NN*NH];
__device__ float g_er[MM*NN*NH];
__device__ int   g_deg[MM*NN];
__device__ int   g_off[MM*(NN+1)];
__device__ int   g_cur[MM*NN];
__device__ int   g_srt[MM*EE];
__device__ float g_w[NN*MM];                   // row = n*3+m
__device__ float g_s[NN*MM];
__device__ float g_wmax[MM];
__device__ float g_den[MM];
__device__ float g_fus[MM*HDIM];

__device__ __forceinline__ void atomicMaxF(float* addr, float v) {
    if (v >= 0.f) atomicMax((int*)addr, __float_as_int(v));
    else          atomicMin((unsigned int*)addr, __float_as_uint(v));
}

// ---------------- init scratch each replay ----------------
__global__ void k_init() {
    int idx = blockIdx.x * blockDim.x + threadIdx.x;
    if (idx < MM*NN) g_deg[idx] = 0;
    if (idx < MM*HDIM) g_fus[idx] = 0.f;
    if (idx < MM) { g_den[idx] = 0.f; g_wmax[idx] = -INFINITY; }
}

// ---------------- feat = h @ fc_w[m]  (tiled fp32 GEMM) ----------------
// BM=64, BN=128 (full), BK=16, 256 threads, 8x4 micro-tile.
__global__ __launch_bounds__(256) void k_gemm_feat(const float* __restrict__ A,
                                                   const float* __restrict__ W) {
    __shared__ float As[64][16];
    __shared__ float Bs[16][128];
    int m    = blockIdx.z;
    int row0 = blockIdx.y * 64;
    int tid  = threadIdx.x;
    int tx   = tid & 31;      // col group: cols tx*4..tx*4+3
    int ty   = tid >> 5;      // row group: rows ty*8..ty*8+7
    const float* Wm = W + (size_t)m * INSZ * HDIM;

    float acc[8][4];
#pragma unroll
    for (int i = 0; i < 8; i++)
#pragma unroll
        for (int j = 0; j < 4; j++) acc[i][j] = 0.f;

    for (int k0 = 0; k0 < INSZ; k0 += 16) {
        {   // A tile: 64x16, one float4 per thread
            int r = tid >> 2, c = tid & 3;
            float4 v = make_float4(0.f, 0.f, 0.f, 0.f);
            int row = row0 + r;
            if (row < NN) v = *(const float4*)(A + (size_t)row * INSZ + k0 + c * 4);
            *(float4*)&As[r][c * 4] = v;
        }
#pragma unroll
        for (int j = 0; j < 2; j++) { // B tile: 16x128, two float4 per thread
            int idx = tid + j * 256;
            int r = idx >> 5, c = idx & 31;
            *(float4*)&Bs[r][c * 4] = *(const float4*)(Wm + (size_t)(k0 + r) * HDIM + c * 4);
        }
        __syncthreads();
#pragma unroll
        for (int kk = 0; kk < 16; kk++) {
            float4 b = *(float4*)&Bs[kk][tx * 4];
#pragma unroll
            for (int i = 0; i < 8; i++) {
                float a = As[ty * 8 + i][kk];
                acc[i][0] += a * b.x; acc[i][1] += a * b.y;
                acc[i][2] += a * b.z; acc[i][3] += a * b.w;
            }
        }
        __syncthreads();
    }
    float* outp = g_feat + (size_t)m * NN * HDIM;
#pragma unroll
    for (int i = 0; i < 8; i++) {
        int row = row0 + ty * 8 + i;
        if (row < NN) {
            float4 v = make_float4(acc[i][0], acc[i][1], acc[i][2], acc[i][3]);
            *(float4*)(outp + (size_t)row * HDIM + tx * 4) = v;
        }
    }
}

// ---------------- el/er per (m,n,h) ----------------
__global__ void k_eler(const float* __restrict__ al, const float* __restrict__ ar) {
    int idx = blockIdx.x * blockDim.x + threadIdx.x;
    if (idx >= MM * NN * NH) return;
    int m = idx / (NN * NH);
    int r = idx - m * NN * NH;
    int n = r / NH, h = r - n * NH;
    const float* f  = g_feat + (size_t)m * NN * HDIM + (size_t)n * HDIM + h * DH;
    const float* a1 = al + (m * NH + h) * DH;
    const float* a2 = ar + (m * NH + h) * DH;
    float sl = 0.f, sr = 0.f;
#pragma unroll
    for (int d = 0; d < DH; d++) {
        float fv = f[d];
        sl += fv * __ldg(a1 + d);
        sr += fv * __ldg(a2 + d);
    }
    g_el[idx] = sl;
    g_er[idx] = sr;
}

// ---------------- CSR build ----------------
__global__ void k_hist(const int* __restrict__ edges) {
    int idx = blockIdx.x * blockDim.x + threadIdx.x;
    if (idx >= MM * EE) return;
    int m = idx / EE, e = idx - m * EE;
    int dst = edges[(size_t)m * 2 * EE + EE + e];
    atomicAdd(&g_deg[m * NN + dst], 1);
}

__global__ void k_scan() {
    __shared__ int sh[1024];
    int m = blockIdx.x;
    int t = threadIdx.x;
    const int CH = (NN + 1023) / 1024; // 49
    int base = t * CH;
    int sum = 0;
    for (int i = 0; i < CH; i++) {
        int idx = base + i;
        if (idx < NN) sum += g_deg[m * NN + idx];
    }
    sh[t] = sum;
    __syncthreads();
    for (int d = 1; d < 1024; d <<= 1) {
        int v = (t >= d) ? sh[t - d] : 0;
        __syncthreads();
        sh[t] += v;
        __syncthreads();
    }
    int run = sh[t] - sum; // exclusive prefix
    for (int i = 0; i < CH; i++) {
        int idx = base + i;
        if (idx < NN) {
            g_off[m * (NN + 1) + idx] = run;
            g_cur[m * NN + idx] = run;
            run += g_deg[m * NN + idx];
        }
    }
    if (t == 1023) g_off[m * (NN + 1) + NN] = sh[1023];
}

__global__ void k_scatter(const int* __restrict__ edges) {
    int idx = blockIdx.x * blockDim.x + threadIdx.x;
    if (idx >= MM * EE) return;
    int m = idx / EE, e = idx - m * EE;
    int src = edges[(size_t)m * 2 * EE + e];
    int dst = edges[(size_t)m * 2 * EE + EE + e];
    int p = atomicAdd(&g_cur[m * NN + dst], 1);
    g_srt[(size_t)m * EE + p] = src;
}

// ---------------- GAT aggregation: warp per dst node, online softmax ----------------
__global__ __launch_bounds__(256) void k_agg() {
    int lane = threadIdx.x & 31;
    int wid  = (blockIdx.x * blockDim.x + threadIdx.x) >> 5;
    int m    = blockIdx.y;
    if (wid >= NN) return;
    int n = wid;
    int h = lane >> 2;                 // head for this lane's 4 dims
    int beg = g_off[m * (NN + 1) + n];
    int end = g_off[m * (NN + 1) + n + 1];
    float ern = g_er[(m * NN + n) * NH + h];
    const float* featm = g_feat + (size_t)m * NN * HDIM;
    const float* elm   = g_el + m * NN * NH;
    const int*   srcs  = g_srt + (size_t)m * EE;

    float mx = -INFINITY, den = 0.f;
    float ax = 0.f, ay = 0.f, az = 0.f, aw = 0.f;
    for (int i = beg; i < end; i++) {
        int s = srcs[i];
        float e = elm[s * NH + h] + ern;
        e = (e > 0.f) ? e : 0.2f * e;          // leaky_relu
        float nm = fmaxf(mx, e);
        float sc = __expf(mx - nm);            // first iter: exp(-inf)=0
        float ex = __expf(e - nm);
        mx = nm;
        den = den * sc + ex;
        float4 f = *(const float4*)(featm + (size_t)s * HDIM + lane * 4);
        ax = ax * sc + ex * f.x;
        ay = ay * sc + ex * f.y;
        az = az * sc + ex * f.z;
        aw = aw * sc + ex * f.w;
    }
    float inv = (end > beg) ? 1.f / den : 0.f;
    float4 o;
    float v;
    v = ax * inv; o.x = (v > 0.f) ? v : expm1f(v);
    v = ay * inv; o.y = (v > 0.f) ? v : expm1f(v);
    v = az * inv; o.z = (v > 0.f) ? v : expm1f(v);
    v = aw * inv; o.w = (v > 0.f) ? v : expm1f(v);
    *(float4*)(g_z + (size_t)(n * MM + m) * HDIM + lane * 4) = o;
}

// ---------------- SA: w = tanh(z @ sa_w1 + b1) @ sa_w2, fused GEMM ----------------
__global__ __launch_bounds__(256) void k_sa(const float* __restrict__ W1,
                                            const float* __restrict__ B1,
                                            const float* __restrict__ W2) {
    __shared__ float As[64][16];
    __shared__ float Bs[16][128];
    const int ROWS = NN * MM;
    int row0 = blockIdx.y * 64;
    int tid  = threadIdx.x;
    int tx   = tid & 31, ty = tid >> 5;

    float acc[8][4];
#pragma unroll
    for (int i = 0; i < 8; i++)
#pragma unroll
        for (int j = 0; j < 4; j++) acc[i][j] = 0.f;

    for (int k0 = 0; k0 < HDIM; k0 += 16) {
        {
            int r = tid >> 2, c = tid & 3;
            float4 v = make_float4(0.f, 0.f, 0.f, 0.f);
            int row = row0 + r;
            if (row < ROWS) v = *(const float4*)(g_z + (size_t)row * HDIM + k0 + c * 4);
            *(float4*)&As[r][c * 4] = v;
        }
#pragma unroll
        for (int j = 0; j < 2; j++) {
            int idx = tid + j * 256;
            int r = idx >> 5, c = idx & 31;
            *(float4*)&Bs[r][c * 4] = *(const float4*)(W1 + (size_t)(k0 + r) * SAH + c * 4);
        }
        __syncthreads();
#pragma unroll
        for (int kk = 0; kk < 16; kk++) {
            float4 b = *(float4*)&Bs[kk][tx * 4];
#pragma unroll
            for (int i = 0; i < 8; i++) {
                float a = As[ty * 8 + i][kk];
                acc[i][0] += a * b.x; acc[i][1] += a * b.y;
                acc[i][2] += a * b.z; acc[i][3] += a * b.w;
            }
        }
        __syncthreads();
    }
    float4 b1 = *(const float4*)(B1 + tx * 4);
    float4 w2 = *(const float4*)(W2 + tx * 4);
#pragma unroll
    for (int i = 0; i < 8; i++) {
        float p = tanhf(acc[i][0] + b1.x) * w2.x
                + tanhf(acc[i][1] + b1.y) * w2.y
                + tanhf(acc[i][2] + b1.z) * w2.z
                + tanhf(acc[i][3] + b1.w) * w2.w;
#pragma unroll
        for (int off = 16; off > 0; off >>= 1)
            p += __shfl_down_sync(0xffffffffu, p, off);
        if (tx == 0) {
            int row = row0 + ty * 8 + i;
            if (row < ROWS) g_w[row] = p;
        }
    }
}

// ---------------- softmax over nodes ----------------
__global__ void k_wmax() {
    float lm0 = -INFINITY, lm1 = -INFINITY, lm2 = -INFINITY;
    for (int n = blockIdx.x * blockDim.x + threadIdx.x; n < NN; n += gridDim.x * blockDim.x) {
        lm0 = fmaxf(lm0, g_w[n * 3 + 0]);
        lm1 = fmaxf(lm1, g_w[n * 3 + 1]);
        lm2 = fmaxf(lm2, g_w[n * 3 + 2]);
    }
#pragma unroll
    for (int off = 16; off > 0; off >>= 1) {
        lm0 = fmaxf(lm0, __shfl_down_sync(0xffffffffu, lm0, off));
        lm1 = fmaxf(lm1, __shfl_down_sync(0xffffffffu, lm1, off));
        lm2 = fmaxf(lm2, __shfl_down_sync(0xffffffffu, lm2, off));
    }
    if ((threadIdx.x & 31) == 0) {
        atomicMaxF(&g_wmax[0], lm0);
        atomicMaxF(&g_wmax[1], lm1);
        atomicMaxF(&g_wmax[2], lm2);
    }
}

__global__ void k_sden() {
    float w0 = g_wmax[0], w1 = g_wmax[1], w2 = g_wmax[2];
    float d0 = 0.f, d1 = 0.f, d2 = 0.f;
    for (int n = blockIdx.x * blockDim.x + threadIdx.x; n < NN; n += gridDim.x * blockDim.x) {
        float s0 = __expf(g_w[n * 3 + 0] - w0);
        float s1 = __expf(g_w[n * 3 + 1] - w1);
        float s2 = __expf(g_w[n * 3 + 2] - w2);
        g_s[n * 3 + 0] = s0; g_s[n * 3 + 1] = s1; g_s[n * 3 + 2] = s2;
        d0 += s0; d1 += s1; d2 += s2;
    }
#pragma unroll
    for (int off = 16; off > 0; off >>= 1) {
        d0 += __shfl_down_sync(0xffffffffu, d0, off);
        d1 += __shfl_down_sync(0xffffffffu, d1, off);
        d2 += __shfl_down_sync(0xffffffffu, d2, off);
    }
    if ((threadIdx.x & 31) == 0) {
        atomicAdd(&g_den[0], d0);
        atomicAdd(&g_den[1], d1);
        atomicAdd(&g_den[2], d2);
    }
}

// fused[m][c] = sum_n s[n][m] * z[n][m][c]   (384 threads own one (m,c) each)
__global__ __launch_bounds__(384) void k_fused() {
    int t = threadIdx.x;            // t = m*128 + c
    int ms = t >> 7;                // m
    float acc = 0.f;
    for (int n = blockIdx.x; n < NN; n += gridDim.x) {
        float s = g_s[n * 3 + ms];
        acc += s * g_z[(size_t)n * ZROW + t];
    }
    atomicAdd(&g_fus[t], acc);
}

__global__ void k_final(const float* __restrict__ PW, const float* __restrict__ PB,
                        float* __restrict__ out) {
    int t = threadIdx.x;
    if (t >= MM * OUTC) return;
    int m = t / OUTC, o = t - m * OUTC;
    float a = 0.f;
#pragma unroll 8
    for (int c = 0; c < HDIM; c++)
        a += g_fus[m * HDIM + c] * __ldg(PW + c * OUTC + o);
    out[t] = a / g_den[m] + __ldg(PB + o);
}

// ---------------- launcher ----------------
extern "C" void kernel_launch(void* const* d_in, const int* in_sizes, int n_in,
                              void* d_out, int out_size) {
    const float* h      = (const float*)d_in[0];
    const int*   edges  = (const int*)d_in[1];
    const float* fc_w   = (const float*)d_in[2];
    const float* attn_l = (const float*)d_in[3];
    const float* attn_r = (const float*)d_in[4];
    const float* sa_w1  = (const float*)d_in[5];
    const float* sa_b1  = (const float*)d_in[6];
    const float* sa_w2  = (const float*)d_in[7];
    const float* pred_w = (const float*)d_in[8];
    const float* pred_b = (const float*)d_in[9];
    float* out = (float*)d_out;

    k_init<<<(MM * NN + 255) / 256, 256>>>();
    k_gemm_feat<<<dim3(1, (NN + 63) / 64, MM), 256>>>(h, fc_w);
    k_eler<<<(MM * NN * NH + 255) / 256, 256>>>(attn_l, attn_r);
    k_hist<<<(MM * EE + 255) / 256, 256>>>(edges);
    k_scan<<<MM, 1024>>>();
    k_scatter<<<(MM * EE + 255) / 256, 256>>>(edges);
    k_agg<<<dim3((NN + 7) / 8, MM), 256>>>();
    k_sa<<<dim3(1, (NN * MM + 63) / 64), 256>>>(sa_w1, sa_b1, sa_w2);
    k_wmax<<<64, 256>>>();
    k_sden<<<196, 256>>>();
    k_fused<<<256, 384>>>();
    k_final<<<1, 32>>>(pred_w, pred_b, out);
}

// round 4
// speedup vs baseline: 1.2767x; 1.2654x over previous
#include <cuda_runtime.h>
#include <cuda_bf16.h>
#include <math.h>
#include <stdint.h>

#define NN   50000
#define EE   800000
#define MM   3
#define INSZ 256
#define HDIM 128
#define NH   8
#define DH   16
#define OUTC 8
#define SAH  128
#define ZROW (MM*HDIM)
#define SAROWS (NN*MM)
#define ASTR 40   // smem row stride in bf16 elements (80B): conflict-free for ldmatrix

__device__ __align__(16) float g_feat[(size_t)MM*NN*HDIM];
__device__ __align__(16) float g_z[(size_t)NN*MM*HDIM];
__device__ float g_el[MM*NN*NH];
__device__ float g_er[MM*NN*NH];
__device__ int   g_deg[MM*NN];
__device__ int   g_off[MM*(NN+1)];
__device__ int   g_cur[MM*NN];
__device__ int   g_srt[MM*EE];
__device__ float g_w[SAROWS];
__device__ float g_s[SAROWS];
__device__ float g_wmax[MM];
__device__ float g_den[MM];
__device__ float g_fus[MM*HDIM];
__device__ __align__(16) __nv_bfloat16 g_wt_hi[MM*HDIM*INSZ];  // [m][n][k]
__device__ __align__(16) __nv_bfloat16 g_wt_lo[MM*HDIM*INSZ];
__device__ __align__(16) __nv_bfloat16 g_w1t_hi[SAH*HDIM];     // [n][k]
__device__ __align__(16) __nv_bfloat16 g_w1t_lo[SAH*HDIM];

__device__ __forceinline__ uint32_t smem_u32(const void* p) {
    uint32_t a;
    asm("{ .reg .u64 t; cvta.to.shared.u64 t, %1; cvt.u32.u64 %0, t; }" : "=r"(a) : "l"(p));
    return a;
}
__device__ __forceinline__ void ldm4(uint32_t* r, uint32_t addr) {
    asm volatile("ldmatrix.sync.aligned.m8n8.x4.shared.b16 {%0,%1,%2,%3}, [%4];"
        : "=r"(r[0]), "=r"(r[1]), "=r"(r[2]), "=r"(r[3]) : "r"(addr));
}
__device__ __forceinline__ void mma16816(float* c, const uint32_t* a, uint32_t b0, uint32_t b1) {
    asm volatile("mma.sync.aligned.m16n8k16.row.col.f32.bf16.bf16.f32 "
        "{%0,%1,%2,%3}, {%4,%5,%6,%7}, {%8,%9}, {%0,%1,%2,%3};"
        : "+f"(c[0]), "+f"(c[1]), "+f"(c[2]), "+f"(c[3])
        : "r"(a[0]), "r"(a[1]), "r"(a[2]), "r"(a[3]), "r"(b0), "r"(b1));
}
__device__ __forceinline__ void cvt_hilo(float4 v, void* hi, void* lo) {
    __nv_bfloat16 h[4], l[4];
    h[0] = __float2bfloat16(v.x); h[1] = __float2bfloat16(v.y);
    h[2] = __float2bfloat16(v.z); h[3] = __float2bfloat16(v.w);
    l[0] = __float2bfloat16(v.x - __bfloat162float(h[0]));
    l[1] = __float2bfloat16(v.y - __bfloat162float(h[1]));
    l[2] = __float2bfloat16(v.z - __bfloat162float(h[2]));
    l[3] = __float2bfloat16(v.w - __bfloat162float(h[3]));
    *(uint2*)hi = *(uint2*)h;
    *(uint2*)lo = *(uint2*)l;
}
__device__ __forceinline__ void atomicMaxF(float* addr, float v) {
    if (v >= 0.f) atomicMax((int*)addr, __float_as_int(v));
    else          atomicMin((unsigned int*)addr, __float_as_uint(v));
}

__global__ void k_init() {
    int idx = blockIdx.x * blockDim.x + threadIdx.x;
    if (idx < MM*NN) g_deg[idx] = 0;
    if (idx < MM*HDIM) g_fus[idx] = 0.f;
    if (idx < MM) { g_den[idx] = 0.f; g_wmax[idx] = -INFINITY; }
}

__global__ void k_prep(const float* __restrict__ fc_w, const float* __restrict__ sa_w1) {
    int idx = blockIdx.x * blockDim.x + threadIdx.x;
    if (idx < MM*HDIM*INSZ) {
        int m = idx / (HDIM*INSZ), r = idx - m*(HDIM*INSZ);
        int n = r / INSZ, k = r - n*INSZ;
        float x = fc_w[((size_t)m*INSZ + k)*HDIM + n];
        __nv_bfloat16 hi = __float2bfloat16(x);
        g_wt_hi[idx] = hi;
        g_wt_lo[idx] = __float2bfloat16(x - __bfloat162float(hi));
    } else {
        int j = idx - MM*HDIM*INSZ;
        if (j < SAH*HDIM) {
            int n = j / HDIM, k = j - n*HDIM;
            float x = sa_w1[(size_t)k*SAH + n];
            __nv_bfloat16 hi = __float2bfloat16(x);
            g_w1t_hi[j] = hi;
            g_w1t_lo[j] = __float2bfloat16(x - __bfloat162float(hi));
        }
    }
}

// ---- feat = h @ fc_w[m], split-bf16 mma.sync ----
__global__ __launch_bounds__(256) void k_feat_mma(const float* __restrict__ A) {
    __shared__ __align__(16) __nv_bfloat16 sAh[128*ASTR], sAl[128*ASTR];
    __shared__ __align__(16) __nv_bfloat16 sBh[128*ASTR], sBl[128*ASTR];
    int tid = threadIdx.x, w = tid >> 5, lane = tid & 31;
    int m = blockIdx.y, row0 = blockIdx.x * 128;
    uint32_t aAh = smem_u32(sAh), aAl = smem_u32(sAl);
    uint32_t aBh = smem_u32(sBh), aBl = smem_u32(sBl);
    float acc[16][4];
#pragma unroll
    for (int j = 0; j < 16; j++)
#pragma unroll
        for (int i = 0; i < 4; i++) acc[j][i] = 0.f;

    const __nv_bfloat16* Bh = g_wt_hi + (size_t)m * HDIM * INSZ;
    const __nv_bfloat16* Bl = g_wt_lo + (size_t)m * HDIM * INSZ;

    for (int kc = 0; kc < 8; kc++) {
        int k0 = kc * 32;
#pragma unroll
        for (int i = 0; i < 4; i++) {   // A: 128 rows x 32 k fp32 -> hi/lo bf16
            int p = i * 256 + tid;
            int r = p >> 3, q = p & 7;
            int node = row0 + r;
            float4 v = make_float4(0.f, 0.f, 0.f, 0.f);
            if (node < NN) v = *(const float4*)(A + (size_t)node * INSZ + k0 + q * 4);
            cvt_hilo(v, &sAh[r*ASTR + q*4], &sAl[r*ASTR + q*4]);
        }
#pragma unroll
        for (int i = 0; i < 2; i++) {   // B: 128 n x 32 k bf16 hi/lo
            int p = i * 256 + tid;
            int r = p >> 2, q = p & 3;
            *(uint4*)&sBh[r*ASTR + q*8] = *(const uint4*)(Bh + (size_t)r * INSZ + k0 + q * 8);
            *(uint4*)&sBl[r*ASTR + q*8] = *(const uint4*)(Bl + (size_t)r * INSZ + k0 + q * 8);
        }
        __syncthreads();
#pragma unroll
        for (int ks = 0; ks < 2; ks++) {
            uint32_t fo = ((lane & 15) * ASTR + ks * 16 + (lane >> 4) * 8) * 2;
            uint32_t ah[4], al[4];
            ldm4(ah, aAh + w * 16 * ASTR * 2 + fo);
            ldm4(al, aAl + w * 16 * ASTR * 2 + fo);
#pragma unroll
            for (int jp = 0; jp < 8; jp++) {
                uint32_t bh[4], bl[4];
                ldm4(bh, aBh + jp * 16 * ASTR * 2 + fo);
                ldm4(bl, aBl + jp * 16 * ASTR * 2 + fo);
                mma16816(acc[2*jp],   ah, bh[0], bh[2]);
                mma16816(acc[2*jp],   ah, bl[0], bl[2]);
                mma16816(acc[2*jp],   al, bh[0], bh[2]);
                mma16816(acc[2*jp+1], ah, bh[1], bh[3]);
                mma16816(acc[2*jp+1], ah, bl[1], bl[3]);
                mma16816(acc[2*jp+1], al, bh[1], bh[3]);
            }
        }
        __syncthreads();
    }
    int g = lane >> 2, t4 = lane & 3;
    int r0 = row0 + w * 16 + g;
    float* outp = g_feat + (size_t)m * NN * HDIM;
#pragma unroll
    for (int j = 0; j < 16; j++) {
        int col = j * 8 + t4 * 2;
        if (r0 < NN)     *(float2*)(outp + (size_t)r0 * HDIM + col)       = make_float2(acc[j][0], acc[j][1]);
        if (r0 + 8 < NN) *(float2*)(outp + (size_t)(r0 + 8) * HDIM + col) = make_float2(acc[j][2], acc[j][3]);
    }
}

// ---- SA: w = tanh(z @ sa_w1 + b1) @ sa_w2, split-bf16 mma.sync + fused epilogue ----
__global__ __launch_bounds__(256) void k_sa_mma(const float* __restrict__ B1,
                                                const float* __restrict__ W2) {
    __shared__ __align__(16) __nv_bfloat16 sAh[128*ASTR], sAl[128*ASTR];
    __shared__ __align__(16) __nv_bfloat16 sBh[128*ASTR], sBl[128*ASTR];
    __shared__ float s_b1[128], s_w2[128];
    int tid = threadIdx.x, w = tid >> 5, lane = tid & 31;
    int row0 = blockIdx.x * 128;
    if (tid < 128) { s_b1[tid] = B1[tid]; s_w2[tid] = W2[tid]; }
    uint32_t aAh = smem_u32(sAh), aAl = smem_u32(sAl);
    uint32_t aBh = smem_u32(sBh), aBl = smem_u32(sBl);
    float acc[16][4];
#pragma unroll
    for (int j = 0; j < 16; j++)
#pragma unroll
        for (int i = 0; i < 4; i++) acc[j][i] = 0.f;

    for (int kc = 0; kc < 4; kc++) {
        int k0 = kc * 32;
#pragma unroll
        for (int i = 0; i < 4; i++) {
            int p = i * 256 + tid;
            int r = p >> 3, q = p & 7;
            int row = row0 + r;
            float4 v = make_float4(0.f, 0.f, 0.f, 0.f);
            if (row < SAROWS) v = *(const float4*)(g_z + (size_t)row * HDIM + k0 + q * 4);
            cvt_hilo(v, &sAh[r*ASTR + q*4], &sAl[r*ASTR + q*4]);
        }
#pragma unroll
        for (int i = 0; i < 2; i++) {
            int p = i * 256 + tid;
            int r = p >> 2, q = p & 3;
            *(uint4*)&sBh[r*ASTR + q*8] = *(const uint4*)(g_w1t_hi + (size_t)r * HDIM + k0 + q * 8);
            *(uint4*)&sBl[r*ASTR + q*8] = *(const uint4*)(g_w1t_lo + (size_t)r * HDIM + k0 + q * 8);
        }
        __syncthreads();
#pragma unroll
        for (int ks = 0; ks < 2; ks++) {
            uint32_t fo = ((lane & 15) * ASTR + ks * 16 + (lane >> 4) * 8) * 2;
            uint32_t ah[4], al[4];
            ldm4(ah, aAh + w * 16 * ASTR * 2 + fo);
            ldm4(al, aAl + w * 16 * ASTR * 2 + fo);
#pragma unroll
            for (int jp = 0; jp < 8; jp++) {
                uint32_t bh[4], bl[4];
                ldm4(bh, aBh + jp * 16 * ASTR * 2 + fo);
                ldm4(bl, aBl + jp * 16 * ASTR * 2 + fo);
                mma16816(acc[2*jp],   ah, bh[0], bh[2]);
                mma16816(acc[2*jp],   ah, bl[0], bl[2]);
                mma16816(acc[2*jp],   al, bh[0], bh[2]);
                mma16816(acc[2*jp+1], ah, bh[1], bh[3]);
                mma16816(acc[2*jp+1], ah, bl[1], bl[3]);
                mma16816(acc[2*jp+1], al, bh[1], bh[3]);
            }
        }
        __syncthreads();
    }
    int g = lane >> 2, t4 = lane & 3;
    float s0 = 0.f, s1 = 0.f;
#pragma unroll
    for (int j = 0; j < 16; j++) {
        int col = j * 8 + t4 * 2;
        float b0 = s_b1[col], b1v = s_b1[col + 1];
        float w0 = s_w2[col], w1v = s_w2[col + 1];
        s0 += tanhf(acc[j][0] + b0) * w0 + tanhf(acc[j][1] + b1v) * w1v;
        s1 += tanhf(acc[j][2] + b0) * w0 + tanhf(acc[j][3] + b1v) * w1v;
    }
    s0 += __shfl_xor_sync(0xffffffffu, s0, 1); s0 += __shfl_xor_sync(0xffffffffu, s0, 2);
    s1 += __shfl_xor_sync(0xffffffffu, s1, 1); s1 += __shfl_xor_sync(0xffffffffu, s1, 2);
    if (t4 == 0) {
        int r0 = row0 + w * 16 + g;
        if (r0 < SAROWS)     g_w[r0]     = s0;
        if (r0 + 8 < SAROWS) g_w[r0 + 8] = s1;
    }
}

__global__ void k_eler(const float* __restrict__ al, const float* __restrict__ ar) {
    int idx = blockIdx.x * blockDim.x + threadIdx.x;
    if (idx >= MM*NN*NH) return;
    int m = idx / (NN*NH), r = idx - m*NN*NH;
    int n = r / NH, h = r - n*NH;
    const float* f  = g_feat + ((size_t)m*NN + n)*HDIM + h*DH;
    const float* a1 = al + (m*NH + h)*DH;
    const float* a2 = ar + (m*NH + h)*DH;
    float sl = 0.f, sr = 0.f;
#pragma unroll
    for (int d = 0; d < DH; d++) { float fv = f[d]; sl += fv*__ldg(a1+d); sr += fv*__ldg(a2+d); }
    g_el[idx] = sl; g_er[idx] = sr;
}

__global__ void k_hist(const int* __restrict__ edges) {
    int idx = blockIdx.x * blockDim.x + threadIdx.x;
    if (idx >= MM*EE) return;
    int m = idx / EE, e = idx - m*EE;
    atomicAdd(&g_deg[m*NN + edges[(size_t)m*2*EE + EE + e]], 1);
}

__global__ void k_scan() {
    __shared__ int sh[1024];
    int m = blockIdx.x, t = threadIdx.x;
    const int CH = (NN + 1023) / 1024;
    int base = t * CH, sum = 0;
    for (int i = 0; i < CH; i++) { int idx = base+i; if (idx < NN) sum += g_deg[m*NN+idx]; }
    sh[t] = sum; __syncthreads();
    for (int d = 1; d < 1024; d <<= 1) {
        int v = (t >= d) ? sh[t-d] : 0; __syncthreads();
        sh[t] += v; __syncthreads();
    }
    int run = sh[t] - sum;
    for (int i = 0; i < CH; i++) {
        int idx = base+i;
        if (idx < NN) { g_off[m*(NN+1)+idx] = run; g_cur[m*NN+idx] = run; run += g_deg[m*NN+idx]; }
    }
    if (t == 1023) g_off[m*(NN+1)+NN] = sh[1023];
}

__global__ void k_scatter(const int* __restrict__ edges) {
    int idx = blockIdx.x * blockDim.x + threadIdx.x;
    if (idx >= MM*EE) return;
    int m = idx / EE, e = idx - m*EE;
    int src = edges[(size_t)m*2*EE + e];
    int dst = edges[(size_t)m*2*EE + EE + e];
    g_srt[(size_t)m*EE + atomicAdd(&g_cur[m*NN + dst], 1)] = src;
}

__global__ __launch_bounds__(256) void k_agg() {
    int lane = threadIdx.x & 31;
    int wid  = (blockIdx.x * blockDim.x + threadIdx.x) >> 5;
    int m    = blockIdx.y;
    if (wid >= NN) return;
    int n = wid, h = lane >> 2;
    int beg = g_off[m*(NN+1)+n], end = g_off[m*(NN+1)+n+1];
    float ern = g_er[(m*NN+n)*NH + h];
    const float* featm = g_feat + (size_t)m*NN*HDIM;
    const float* elm   = g_el + m*NN*NH;
    const int*   srcs  = g_srt + (size_t)m*EE;
    float mx = -INFINITY, den = 0.f, ax = 0.f, ay = 0.f, az = 0.f, aw = 0.f;
    for (int i = beg; i < end; i++) {
        int s = srcs[i];
        float e = elm[s*NH + h] + ern;
        e = (e > 0.f) ? e : 0.2f*e;
        float nm = fmaxf(mx, e);
        float sc = __expf(mx - nm), ex = __expf(e - nm);
        mx = nm; den = den*sc + ex;
        float4 f = *(const float4*)(featm + (size_t)s*HDIM + lane*4);
        ax = ax*sc + ex*f.x; ay = ay*sc + ex*f.y;
        az = az*sc + ex*f.z; aw = aw*sc + ex*f.w;
    }
    float inv = (end > beg) ? 1.f/den : 0.f;
    float4 o; float v;
    v = ax*inv; o.x = (v > 0.f) ? v : expm1f(v);
    v = ay*inv; o.y = (v > 0.f) ? v : expm1f(v);
    v = az*inv; o.z = (v > 0.f) ? v : expm1f(v);
    v = aw*inv; o.w = (v > 0.f) ? v : expm1f(v);
    *(float4*)(g_z + (size_t)(n*MM + m)*HDIM + lane*4) = o;
}

__global__ void k_wmax() {
    float lm0 = -INFINITY, lm1 = -INFINITY, lm2 = -INFINITY;
    for (int n = blockIdx.x*blockDim.x + threadIdx.x; n < NN; n += gridDim.x*blockDim.x) {
        lm0 = fmaxf(lm0, g_w[n*3+0]); lm1 = fmaxf(lm1, g_w[n*3+1]); lm2 = fmaxf(lm2, g_w[n*3+2]);
    }
#pragma unroll
    for (int off = 16; off > 0; off >>= 1) {
        lm0 = fmaxf(lm0, __shfl_down_sync(0xffffffffu, lm0, off));
        lm1 = fmaxf(lm1, __shfl_down_sync(0xffffffffu, lm1, off));
        lm2 = fmaxf(lm2, __shfl_down_sync(0xffffffffu, lm2, off));
    }
    if ((threadIdx.x & 31) == 0) {
        atomicMaxF(&g_wmax[0], lm0); atomicMaxF(&g_wmax[1], lm1); atomicMaxF(&g_wmax[2], lm2);
    }
}

__global__ void k_sden() {
    float w0 = g_wmax[0], w1 = g_wmax[1], w2 = g_wmax[2];
    float d0 = 0.f, d1 = 0.f, d2 = 0.f;
    for (int n = blockIdx.x*blockDim.x + threadIdx.x; n < NN; n += gridDim.x*blockDim.x) {
        float s0 = __expf(g_w[n*3+0]-w0), s1 = __expf(g_w[n*3+1]-w1), s2 = __expf(g_w[n*3+2]-w2);
        g_s[n*3+0] = s0; g_s[n*3+1] = s1; g_s[n*3+2] = s2;
        d0 += s0; d1 += s1; d2 += s2;
    }
#pragma unroll
    for (int off = 16; off > 0; off >>= 1) {
        d0 += __shfl_down_sync(0xffffffffu, d0, off);
        d1 += __shfl_down_sync(0xffffffffu, d1, off);
        d2 += __shfl_down_sync(0xffffffffu, d2, off);
    }
    if ((threadIdx.x & 31) == 0) {
        atomicAdd(&g_den[0], d0); atomicAdd(&g_den[1], d1); atomicAdd(&g_den[2], d2);
    }
}

__global__ __launch_bounds__(384) void k_fused() {
    int t = threadIdx.x, ms = t >> 7;
    float acc = 0.f;
    for (int n = blockIdx.x; n < NN; n += gridDim.x)
        acc += g_s[n*3 + ms] * g_z[(size_t)n*ZROW + t];
    atomicAdd(&g_fus[t], acc);
}

__global__ void k_final(const float* __restrict__ PW, const float* __restrict__ PB,
                        float* __restrict__ out) {
    int t = threadIdx.x;
    if (t >= MM*OUTC) return;
    int m = t / OUTC, o = t - m*OUTC;
    float a = 0.f;
#pragma unroll 8
    for (int c = 0; c < HDIM; c++) a += g_fus[m*HDIM + c] * __ldg(PW + c*OUTC + o);
    out[t] = a / g_den[m] + __ldg(PB + o);
}

extern "C" void kernel_launch(void* const* d_in, const int* in_sizes, int n_in,
                              void* d_out, int out_size) {
    const float* h      = (const float*)d_in[0];
    const int*   edges  = (const int*)d_in[1];
    const float* fc_w   = (const float*)d_in[2];
    const float* attn_l = (const float*)d_in[3];
    const float* attn_r = (const float*)d_in[4];
    const float* sa_w1  = (const float*)d_in[5];
    const float* sa_b1  = (const float*)d_in[6];
    const float* sa_w2  = (const float*)d_in[7];
    const float* pred_w = (const float*)d_in[8];
    const float* pred_b = (const float*)d_in[9];
    float* out = (float*)d_out;

    k_init<<<(MM*NN + 255)/256, 256>>>();
    k_prep<<<(MM*HDIM*INSZ + SAH*HDIM + 255)/256, 256>>>(fc_w, sa_w1);
    k_feat_mma<<<dim3((NN + 127)/128, MM), 256>>>(h);
    k_eler<<<(MM*NN*NH + 255)/256, 256>>>(attn_l, attn_r);
    k_hist<<<(MM*EE + 255)/256, 256>>>(edges);
    k_scan<<<MM, 1024>>>();
    k_scatter<<<(MM*EE + 255)/256, 256>>>(edges);
    k_agg<<<dim3((NN + 7)/8, MM), 256>>>();
    k_sa_mma<<<(SAROWS + 127)/128, 256>>>(sa_b1, sa_w2);
    k_wmax<<<64, 256>>>();
    k_sden<<<196, 256>>>();
    k_fused<<<256, 384>>>();
    k_final<<<1, 32>>>(pred_w, pred_b, out);
}

// round 6
// speedup vs baseline: 1.4454x; 1.1321x over previous
#include <cuda_runtime.h>
#include <cuda_bf16.h>
#include <math.h>
#include <stdint.h>

#define NN   50000
#define EE   800000
#define MM   3
#define INSZ 256
#define HDIM 128
#define NH   8
#define DH   16
#define OUTC 8
#define SAH  128
#define ZROW (MM*HDIM)
#define SAROWS (NN*MM)
#define ASTR 40

__device__ __align__(16) __nv_bfloat16 g_feat16[(size_t)MM*NN*HDIM];
__device__ __align__(16) float g_z[(size_t)NN*MM*HDIM];
__device__ float g_el[MM*NN*NH];
__device__ float g_er[MM*NN*NH];
__device__ int   g_deg[MM*NN];
__device__ int   g_off[MM*(NN+1)];
__device__ int   g_cur[MM*NN];
__device__ int   g_srt[MM*EE];
__device__ float g_w[SAROWS];
__device__ float g_s[SAROWS];
__device__ float g_wmax[MM];
__device__ float g_den[MM];
__device__ float g_fus[MM*HDIM];
__device__ __align__(16) __nv_bfloat16 g_wt_hi[MM*HDIM*INSZ];
__device__ __align__(16) __nv_bfloat16 g_wt_lo[MM*HDIM*INSZ];
__device__ __align__(16) __nv_bfloat16 g_w1t_hi[SAH*HDIM];
__device__ __align__(16) __nv_bfloat16 g_w1t_lo[SAH*HDIM];

__device__ __forceinline__ uint32_t smem_u32(const void* p) {
    uint32_t a;
    asm("{ .reg .u64 t; cvta.to.shared.u64 t, %1; cvt.u32.u64 %0, t; }" : "=r"(a) : "l"(p));
    return a;
}
__device__ __forceinline__ void ldm4(uint32_t* r, uint32_t addr) {
    asm volatile("ldmatrix.sync.aligned.m8n8.x4.shared.b16 {%0,%1,%2,%3}, [%4];"
        : "=r"(r[0]), "=r"(r[1]), "=r"(r[2]), "=r"(r[3]) : "r"(addr));
}
__device__ __forceinline__ void mma16816(float* c, const uint32_t* a, uint32_t b0, uint32_t b1) {
    asm volatile("mma.sync.aligned.m16n8k16.row.col.f32.bf16.bf16.f32 "
        "{%0,%1,%2,%3}, {%4,%5,%6,%7}, {%8,%9}, {%0,%1,%2,%3};"
        : "+f"(c[0]), "+f"(c[1]), "+f"(c[2]), "+f"(c[3])
        : "r"(a[0]), "r"(a[1]), "r"(a[2]), "r"(a[3]), "r"(b0), "r"(b1));
}
__device__ __forceinline__ void cvt_hilo(float4 v, void* hi, void* lo) {
    __nv_bfloat16 h[4], l[4];
    h[0] = __float2bfloat16(v.x); h[1] = __float2bfloat16(v.y);
    h[2] = __float2bfloat16(v.z); h[3] = __float2bfloat16(v.w);
    l[0] = __float2bfloat16(v.x - __bfloat162float(h[0]));
    l[1] = __float2bfloat16(v.y - __bfloat162float(h[1]));
    l[2] = __float2bfloat16(v.z - __bfloat162float(h[2]));
    l[3] = __float2bfloat16(v.w - __bfloat162float(h[3]));
    *(uint2*)hi = *(uint2*)h;
    *(uint2*)lo = *(uint2*)l;
}
__device__ __forceinline__ void atomicMaxF(float* addr, float v) {
    if (v >= 0.f) atomicMax((int*)addr, __float_as_int(v));
    else          atomicMin((unsigned int*)addr, __float_as_uint(v));
}

__global__ void k_init() {
    int idx = blockIdx.x * blockDim.x + threadIdx.x;
    if (idx < MM*NN) g_deg[idx] = 0;
    if (idx < MM*HDIM) g_fus[idx] = 0.f;
    if (idx < MM) { g_den[idx] = 0.f; g_wmax[idx] = -INFINITY; }
}

__global__ void k_prep(const float* __restrict__ fc_w, const float* __restrict__ sa_w1) {
    int idx = blockIdx.x * blockDim.x + threadIdx.x;
    if (idx < MM*HDIM*INSZ) {
        int m = idx / (HDIM*INSZ), r = idx - m*(HDIM*INSZ);
        int n = r / INSZ, k = r - n*INSZ;
        float x = fc_w[((size_t)m*INSZ + k)*HDIM + n];
        __nv_bfloat16 hi = __float2bfloat16(x);
        g_wt_hi[idx] = hi;
        g_wt_lo[idx] = __float2bfloat16(x - __bfloat162float(hi));
    } else {
        int j = idx - MM*HDIM*INSZ;
        if (j < SAH*HDIM) {
            int n = j / HDIM, k = j - n*HDIM;
            float x = sa_w1[(size_t)k*SAH + n];
            __nv_bfloat16 hi = __float2bfloat16(x);
            g_w1t_hi[j] = hi;
            g_w1t_lo[j] = __float2bfloat16(x - __bfloat162float(hi));
        }
    }
}

// ---- feat = h @ fc_w[m], split-bf16 mma.sync; epilogue: bf16 feat + fused el/er ----
__global__ __launch_bounds__(256) void k_feat_mma(const float* __restrict__ A,
                                                  const float* __restrict__ AL,
                                                  const float* __restrict__ AR) {
    __shared__ __align__(16) __nv_bfloat16 sAh[128*ASTR], sAl[128*ASTR];
    __shared__ __align__(16) __nv_bfloat16 sBh[128*ASTR], sBl[128*ASTR];
    __shared__ float s_al[128], s_ar[128];
    int tid = threadIdx.x, w = tid >> 5, lane = tid & 31;
    int m = blockIdx.y, row0 = blockIdx.x * 128;
    if (tid < 128) { s_al[tid] = AL[m*HDIM + tid]; s_ar[tid] = AR[m*HDIM + tid]; }
    uint32_t aAh = smem_u32(sAh), aAl = smem_u32(sAl);
    uint32_t aBh = smem_u32(sBh), aBl = smem_u32(sBl);
    float acc[16][4];
#pragma unroll
    for (int j = 0; j < 16; j++)
#pragma unroll
        for (int i = 0; i < 4; i++) acc[j][i] = 0.f;

    const __nv_bfloat16* Bh = g_wt_hi + (size_t)m * HDIM * INSZ;
    const __nv_bfloat16* Bl = g_wt_lo + (size_t)m * HDIM * INSZ;

    for (int kc = 0; kc < 8; kc++) {
        int k0 = kc * 32;
#pragma unroll
        for (int i = 0; i < 4; i++) {
            int p = i * 256 + tid;
            int r = p >> 3, q = p & 7;
            int node = row0 + r;
            float4 v = make_float4(0.f, 0.f, 0.f, 0.f);
            if (node < NN) v = *(const float4*)(A + (size_t)node * INSZ + k0 + q * 4);
            cvt_hilo(v, &sAh[r*ASTR + q*4], &sAl[r*ASTR + q*4]);
        }
#pragma unroll
        for (int i = 0; i < 2; i++) {
            int p = i * 256 + tid;
            int r = p >> 2, q = p & 3;
            *(uint4*)&sBh[r*ASTR + q*8] = *(const uint4*)(Bh + (size_t)r * INSZ + k0 + q * 8);
            *(uint4*)&sBl[r*ASTR + q*8] = *(const uint4*)(Bl + (size_t)r * INSZ + k0 + q * 8);
        }
        __syncthreads();
#pragma unroll
        for (int ks = 0; ks < 2; ks++) {
            uint32_t fo = ((lane & 15) * ASTR + ks * 16 + (lane >> 4) * 8) * 2;
            uint32_t ah[4], al[4];
            ldm4(ah, aAh + w * 16 * ASTR * 2 + fo);
            ldm4(al, aAl + w * 16 * ASTR * 2 + fo);
#pragma unroll
            for (int jp = 0; jp < 8; jp++) {
                uint32_t bh[4], bl[4];
                ldm4(bh, aBh + jp * 16 * ASTR * 2 + fo);
                ldm4(bl, aBl + jp * 16 * ASTR * 2 + fo);
                mma16816(acc[2*jp],   ah, bh[0], bh[2]);
                mma16816(acc[2*jp],   ah, bl[0], bl[2]);
                mma16816(acc[2*jp],   al, bh[0], bh[2]);
                mma16816(acc[2*jp+1], ah, bh[1], bh[3]);
                mma16816(acc[2*jp+1], ah, bl[1], bl[3]);
                mma16816(acc[2*jp+1], al, bh[1], bh[3]);
            }
        }
        __syncthreads();
    }
    int g = lane >> 2, t4 = lane & 3;
    int r0 = row0 + w * 16 + g;
    __nv_bfloat16* outp = g_feat16 + (size_t)m * NN * HDIM;
#pragma unroll
    for (int j = 0; j < 16; j++) {
        int col = j * 8 + t4 * 2;
        if (r0 < NN)
            *(__nv_bfloat162*)(outp + (size_t)r0 * HDIM + col) =
                __float22bfloat162_rn(make_float2(acc[j][0], acc[j][1]));
        if (r0 + 8 < NN)
            *(__nv_bfloat162*)(outp + (size_t)(r0 + 8) * HDIM + col) =
                __float22bfloat162_rn(make_float2(acc[j][2], acc[j][3]));
    }
#pragma unroll
    for (int h = 0; h < NH; h++) {
        float pl0 = 0.f, pr0 = 0.f, pl1 = 0.f, pr1 = 0.f;
#pragma unroll
        for (int jj = 2*h; jj <= 2*h+1; jj++) {
            int c0 = jj * 8 + t4 * 2, c1 = c0 + 1;
            float a0 = s_al[c0], a1 = s_al[c1], b0 = s_ar[c0], b1 = s_ar[c1];
            pl0 += acc[jj][0]*a0 + acc[jj][1]*a1;
            pr0 += acc[jj][0]*b0 + acc[jj][1]*b1;
            pl1 += acc[jj][2]*a0 + acc[jj][3]*a1;
            pr1 += acc[jj][2]*b0 + acc[jj][3]*b1;
        }
        pl0 += __shfl_xor_sync(0xffffffffu, pl0, 1); pl0 += __shfl_xor_sync(0xffffffffu, pl0, 2);
        pr0 += __shfl_xor_sync(0xffffffffu, pr0, 1); pr0 += __shfl_xor_sync(0xffffffffu, pr0, 2);
        pl1 += __shfl_xor_sync(0xffffffffu, pl1, 1); pl1 += __shfl_xor_sync(0xffffffffu, pl1, 2);
        pr1 += __shfl_xor_sync(0xffffffffu, pr1, 1); pr1 += __shfl_xor_sync(0xffffffffu, pr1, 2);
        if (t4 == 0) {
            if (r0 < NN) {
                g_el[(m*NN + r0)*NH + h] = pl0;
                g_er[(m*NN + r0)*NH + h] = pr0;
            }
            if (r0 + 8 < NN) {
                g_el[(m*NN + r0 + 8)*NH + h] = pl1;
                g_er[(m*NN + r0 + 8)*NH + h] = pr1;
            }
        }
    }
}

// ---- SA GEMM + fused tanh epilogue ----
__global__ __launch_bounds__(256) void k_sa_mma(const float* __restrict__ B1,
                                                const float* __restrict__ W2) {
    __shared__ __align__(16) __nv_bfloat16 sAh[128*ASTR], sAl[128*ASTR];
    __shared__ __align__(16) __nv_bfloat16 sBh[128*ASTR], sBl[128*ASTR];
    __shared__ float s_b1[128], s_w2[128];
    int tid = threadIdx.x, w = tid >> 5, lane = tid & 31;
    int row0 = blockIdx.x * 128;
    if (tid < 128) { s_b1[tid] = B1[tid]; s_w2[tid] = W2[tid]; }
    uint32_t aAh = smem_u32(sAh), aAl = smem_u32(sAl);
    uint32_t aBh = smem_u32(sBh), aBl = smem_u32(sBl);
    float acc[16][4];
#pragma unroll
    for (int j = 0; j < 16; j++)
#pragma unroll
        for (int i = 0; i < 4; i++) acc[j][i] = 0.f;

    for (int kc = 0; kc < 4; kc++) {
        int k0 = kc * 32;
#pragma unroll
        for (int i = 0; i < 4; i++) {
            int p = i * 256 + tid;
            int r = p >> 3, q = p & 7;
            int row = row0 + r;
            float4 v = make_float4(0.f, 0.f, 0.f, 0.f);
            if (row < SAROWS) v = *(const float4*)(g_z + (size_t)row * HDIM + k0 + q * 4);
            cvt_hilo(v, &sAh[r*ASTR + q*4], &sAl[r*ASTR + q*4]);
        }
#pragma unroll
        for (int i = 0; i < 2; i++) {
            int p = i * 256 + tid;
            int r = p >> 2, q = p & 3;
            *(uint4*)&sBh[r*ASTR + q*8] = *(const uint4*)(g_w1t_hi + (size_t)r * HDIM + k0 + q * 8);
            *(uint4*)&sBl[r*ASTR + q*8] = *(const uint4*)(g_w1t_lo + (size_t)r * HDIM + k0 + q * 8);
        }
        __syncthreads();
#pragma unroll
        for (int ks = 0; ks < 2; ks++) {
            uint32_t fo = ((lane & 15) * ASTR + ks * 16 + (lane >> 4) * 8) * 2;
            uint32_t ah[4], al[4];
            ldm4(ah, aAh + w * 16 * ASTR * 2 + fo);
            ldm4(al, aAl + w * 16 * ASTR * 2 + fo);
#pragma unroll
            for (int jp = 0; jp < 8; jp++) {
                uint32_t bh[4], bl[4];
                ldm4(bh, aBh + jp * 16 * ASTR * 2 + fo);
                ldm4(bl, aBl + jp * 16 * ASTR * 2 + fo);
                mma16816(acc[2*jp],   ah, bh[0], bh[2]);
                mma16816(acc[2*jp],   ah, bl[0], bl[2]);
                mma16816(acc[2*jp],   al, bh[0], bh[2]);
                mma16816(acc[2*jp+1], ah, bh[1], bh[3]);
                mma16816(acc[2*jp+1], ah, bl[1], bl[3]);
                mma16816(acc[2*jp+1], al, bh[1], bh[3]);
            }
        }
        __syncthreads();
    }
    int g = lane >> 2, t4 = lane & 3;
    float s0 = 0.f, s1 = 0.f;
#pragma unroll
    for (int j = 0; j < 16; j++) {
        int col = j * 8 + t4 * 2;
        float b0 = s_b1[col], b1v = s_b1[col + 1];
        float w0 = s_w2[col], w1v = s_w2[col + 1];
        s0 += tanhf(acc[j][0] + b0) * w0 + tanhf(acc[j][1] + b1v) * w1v;
        s1 += tanhf(acc[j][2] + b0) * w0 + tanhf(acc[j][3] + b1v) * w1v;
    }
    s0 += __shfl_xor_sync(0xffffffffu, s0, 1); s0 += __shfl_xor_sync(0xffffffffu, s0, 2);
    s1 += __shfl_xor_sync(0xffffffffu, s1, 1); s1 += __shfl_xor_sync(0xffffffffu, s1, 2);
    if (t4 == 0) {
        int r0 = row0 + w * 16 + g;
        if (r0 < SAROWS)     g_w[r0]     = s0;
        if (r0 + 8 < SAROWS) g_w[r0 + 8] = s1;
    }
}

__global__ void k_hist(const int* __restrict__ edges) {
    int idx = blockIdx.x * blockDim.x + threadIdx.x;
    if (idx >= MM*EE) return;
    int m = idx / EE, e = idx - m*EE;
    atomicAdd(&g_deg[m*NN + edges[(size_t)m*2*EE + EE + e]], 1);
}

__global__ void k_scan() {
    __shared__ int sh[1024];
    int m = blockIdx.x, t = threadIdx.x;
    const int CH = (NN + 1023) / 1024;
    int base = t * CH, sum = 0;
    for (int i = 0; i < CH; i++) { int idx = base+i; if (idx < NN) sum += g_deg[m*NN+idx]; }
    sh[t] = sum; __syncthreads();
    for (int d = 1; d < 1024; d <<= 1) {
        int v = (t >= d) ? sh[t-d] : 0; __syncthreads();
        sh[t] += v; __syncthreads();
    }
    int run = sh[t] - sum;
    for (int i = 0; i < CH; i++) {
        int idx = base+i;
        if (idx < NN) { g_off[m*(NN+1)+idx] = run; g_cur[m*NN+idx] = run; run += g_deg[m*NN+idx]; }
    }
    if (t == 1023) g_off[m*(NN+1)+NN] = sh[1023];
}

__global__ void k_scatter(const int* __restrict__ edges) {
    int idx = blockIdx.x * blockDim.x + threadIdx.x;
    if (idx >= MM*EE) return;
    int m = idx / EE, e = idx - m*EE;
    int src = edges[(size_t)m*2*EE + e];
    int dst = edges[(size_t)m*2*EE + EE + e];
    g_srt[(size_t)m*EE + atomicAdd(&g_cur[m*NN + dst], 1)] = src;
}

// ---- GAT aggregation: warp/dst, bf16 feat gather, exact softmax (no max) ----
__global__ __launch_bounds__(256) void k_agg() {
    int lane = threadIdx.x & 31;
    int wid  = (blockIdx.x * blockDim.x + threadIdx.x) >> 5;
    int m    = blockIdx.y;
    if (wid >= NN) return;
    int n = wid, h = lane >> 2;
    int beg = g_off[m*(NN+1)+n], end = g_off[m*(NN+1)+n+1];
    float ern = g_er[(m*NN+n)*NH + h];
    const __nv_bfloat16* featm = g_feat16 + (size_t)m*NN*HDIM;
    const float* elm = g_el + m*NN*NH;
    const int*   srcs = g_srt + (size_t)m*EE;
    float den = 0.f, ax = 0.f, ay = 0.f, az = 0.f, aw = 0.f;
    for (int i = beg; i < end; i++) {
        int s = srcs[i];
        float e = elm[s*NH + h] + ern;
        e = (e > 0.f) ? e : 0.2f*e;
        float ex = __expf(e);
        den += ex;
        uint2 f = *(const uint2*)(featm + (size_t)s*HDIM + lane*4);
        float2 v0 = __bfloat1622float2(*(__nv_bfloat162*)&f.x);
        float2 v1 = __bfloat1622float2(*(__nv_bfloat162*)&f.y);
        ax += ex*v0.x; ay += ex*v0.y; az += ex*v1.x; aw += ex*v1.y;
    }
    float inv = (end > beg) ? 1.f/den : 0.f;
    float4 o; float v;
    v = ax*inv; o.x = (v > 0.f) ? v : expm1f(v);
    v = ay*inv; o.y = (v > 0.f) ? v : expm1f(v);
    v = az*inv; o.z = (v > 0.f) ? v : expm1f(v);
    v = aw*inv; o.w = (v > 0.f) ? v : expm1f(v);
    *(float4*)(g_z + (size_t)(n*MM + m)*HDIM + lane*4) = o;
}

__global__ void k_wmax() {
    float lm0 = -INFINITY, lm1 = -INFINITY, lm2 = -INFINITY;
    for (int n = blockIdx.x*blockDim.x + threadIdx.x; n < NN; n += gridDim.x*blockDim.x) {
        lm0 = fmaxf(lm0, g_w[n*3+0]); lm1 = fmaxf(lm1, g_w[n*3+1]); lm2 = fmaxf(lm2, g_w[n*3+2]);
    }
#pragma unroll
    for (int off = 16; off > 0; off >>= 1) {
        lm0 = fmaxf(lm0, __shfl_down_sync(0xffffffffu, lm0, off));
        lm1 = fmaxf(lm1, __shfl_down_sync(0xffffffffu, lm1, off));
        lm2 = fmaxf(lm2, __shfl_down_sync(0xffffffffu, lm2, off));
    }
    if ((threadIdx.x & 31) == 0) {
        atomicMaxF(&g_wmax[0], lm0); atomicMaxF(&g_wmax[1], lm1); atomicMaxF(&g_wmax[2], lm2);
    }
}

__global__ void k_sden() {
    float w0 = g_wmax[0], w1 = g_wmax[1], w2 = g_wmax[2];
    float d0 = 0.f, d1 = 0.f, d2 = 0.f;
    for (int n = blockIdx.x*blockDim.x + threadIdx.x; n < NN; n += gridDim.x*blockDim.x) {
        float s0 = __expf(g_w[n*3+0]-w0), s1 = __expf(g_w[n*3+1]-w1), s2 = __expf(g_w[n*3+2]-w2);
        g_s[n*3+0] = s0; g_s[n*3+1] = s1; g_s[n*3+2] = s2;
        d0 += s0; d1 += s1; d2 += s2;
    }
#pragma unroll
    for (int off = 16; off > 0; off >>= 1) {
        d0 += __shfl_down_sync(0xffffffffu, d0, off);
        d1 += __shfl_down_sync(0xffffffffu, d1, off);
        d2 += __shfl_down_sync(0xffffffffu, d2, off);
    }
    if ((threadIdx.x & 31) == 0) {
        atomicAdd(&g_den[0], d0); atomicAdd(&g_den[1], d1); atomicAdd(&g_den[2], d2);
    }
}

__global__ __launch_bounds__(384) void k_fused() {
    int t = threadIdx.x, ms = t >> 7;
    float acc = 0.f;
    for (int n = blockIdx.x; n < NN; n += gridDim.x)
        acc += g_s[n*3 + ms] * g_z[(size_t)n*ZROW + t];
    atomicAdd(&g_fus[t], acc);
}

__global__ void k_final(const float* __restrict__ PW, const float* __restrict__ PB,
                        float* __restrict__ out) {
    int t = threadIdx.x;
    if (t >= MM*OUTC) return;
    int m = t / OUTC, o = t - m*OUTC;
    float a = 0.f;
#pragma unroll 8
    for (int c = 0; c < HDIM; c++) a += g_fus[m*HDIM + c] * __ldg(PW + c*OUTC + o);
    out[t] = a / g_den[m] + __ldg(PB + o);
}

extern "C" void kernel_launch(void* const* d_in, const int* in_sizes, int n_in,
                              void* d_out, int out_size) {
    const float* h      = (const float*)d_in[0];
    const int*   edges  = (const int*)d_in[1];
    const float* fc_w   = (const float*)d_in[2];
    const float* attn_l = (const float*)d_in[3];
    const float* attn_r = (const float*)d_in[4];
    const float* sa_w1  = (const float*)d_in[5];
    const float* sa_b1  = (const float*)d_in[6];
    const float* sa_w2  = (const float*)d_in[7];
    const float* pred_w = (const float*)d_in[8];
    const float* pred_b = (const float*)d_in[9];
    float* out = (float*)d_out;

    k_init<<<(MM*NN + 255)/256, 256>>>();
    k_prep<<<(MM*HDIM*INSZ + SAH*HDIM + 255)/256, 256>>>(fc_w, sa_w1);
    k_hist<<<(MM*EE + 255)/256, 256>>>(edges);
    k_feat_mma<<<dim3((NN + 127)/128, MM), 256>>>(h, attn_l, attn_r);
    k_scan<<<MM, 1024>>>();
    k_scatter<<<(MM*EE + 255)/256, 256>>>(edges);
    k_agg<<<dim3((NN + 7)/8, MM), 256>>>();
    k_sa_mma<<<(SAROWS + 127)/128, 256>>>(sa_b1, sa_w2);
    k_wmax<<<64, 256>>>();
    k_sden<<<196, 256>>>();
    k_fused<<<256, 384>>>();
    k_final<<<1, 32>>>(pred_w, pred_b, out);
}

// round 7
// speedup vs baseline: 1.4988x; 1.0370x over previous
#include <cuda_runtime.h>
#include <cuda_bf16.h>
#include <math.h>
#include <stdint.h>

#define NN   50000
#define EE   800000
#define MM   3
#define INSZ 256
#define HDIM 128
#define NH   8
#define DH   16
#define OUTC 8
#define SAH  128
#define ZROW (MM*HDIM)
#define SAROWS (NN*MM)
#define ASTR 40

__device__ __align__(16) __nv_bfloat16 g_feat16[(size_t)MM*NN*HDIM];
__device__ __align__(16) __nv_bfloat16 g_z_hi[(size_t)SAROWS*HDIM];
__device__ __align__(16) __nv_bfloat16 g_z_lo[(size_t)SAROWS*HDIM];
__device__ float g_el[MM*NN*NH];
__device__ float g_er[MM*NN*NH];
__device__ int   g_deg[MM*NN];
__device__ int   g_off[MM*(NN+1)];
__device__ int   g_cur[MM*NN];
__device__ int   g_srt[MM*EE];
__device__ float g_w[SAROWS];
__device__ float g_s[SAROWS];
__device__ float g_wmax[MM];
__device__ float g_den[MM];
__device__ float g_fus[MM*HDIM];
__device__ __align__(16) __nv_bfloat16 g_wt_hi[MM*HDIM*INSZ];
__device__ __align__(16) __nv_bfloat16 g_wt_lo[MM*HDIM*INSZ];
__device__ __align__(16) __nv_bfloat16 g_w1t_hi[SAH*HDIM];
__device__ __align__(16) __nv_bfloat16 g_w1t_lo[SAH*HDIM];

__device__ __forceinline__ uint32_t smem_u32(const void* p) {
    uint32_t a;
    asm("{ .reg .u64 t; cvta.to.shared.u64 t, %1; cvt.u32.u64 %0, t; }" : "=r"(a) : "l"(p));
    return a;
}
__device__ __forceinline__ void cp_async16(uint32_t saddr, const void* g) {
    asm volatile("cp.async.cg.shared.global [%0], [%1], 16;" :: "r"(saddr), "l"(g));
}
#define CP_COMMIT() asm volatile("cp.async.commit_group;" ::: "memory")
#define CP_WAIT0()  asm volatile("cp.async.wait_group 0;" ::: "memory")
__device__ __forceinline__ void ldm4(uint32_t* r, uint32_t addr) {
    asm volatile("ldmatrix.sync.aligned.m8n8.x4.shared.b16 {%0,%1,%2,%3}, [%4];"
        : "=r"(r[0]), "=r"(r[1]), "=r"(r[2]), "=r"(r[3]) : "r"(addr));
}
__device__ __forceinline__ void mma16816(float* c, const uint32_t* a, uint32_t b0, uint32_t b1) {
    asm volatile("mma.sync.aligned.m16n8k16.row.col.f32.bf16.bf16.f32 "
        "{%0,%1,%2,%3}, {%4,%5,%6,%7}, {%8,%9}, {%0,%1,%2,%3};"
        : "+f"(c[0]), "+f"(c[1]), "+f"(c[2]), "+f"(c[3])
        : "r"(a[0]), "r"(a[1]), "r"(a[2]), "r"(a[3]), "r"(b0), "r"(b1));
}
__device__ __forceinline__ void cvt_hilo(float4 v, void* hi, void* lo) {
    __nv_bfloat16 h[4], l[4];
    h[0] = __float2bfloat16(v.x); h[1] = __float2bfloat16(v.y);
    h[2] = __float2bfloat16(v.z); h[3] = __float2bfloat16(v.w);
    l[0] = __float2bfloat16(v.x - __bfloat162float(h[0]));
    l[1] = __float2bfloat16(v.y - __bfloat162float(h[1]));
    l[2] = __float2bfloat16(v.z - __bfloat162float(h[2]));
    l[3] = __float2bfloat16(v.w - __bfloat162float(h[3]));
    *(uint2*)hi = *(uint2*)h;
    *(uint2*)lo = *(uint2*)l;
}
__device__ __forceinline__ void atomicMaxF(float* addr, float v) {
    if (v >= 0.f) atomicMax((int*)addr, __float_as_int(v));
    else          atomicMin((unsigned int*)addr, __float_as_uint(v));
}

__global__ void k_init() {
    int idx = blockIdx.x * blockDim.x + threadIdx.x;
    if (idx < MM*NN) g_deg[idx] = 0;
    if (idx < MM*HDIM) g_fus[idx] = 0.f;
    if (idx < MM) { g_den[idx] = 0.f; g_wmax[idx] = -INFINITY; }
}

__global__ void k_prep(const float* __restrict__ fc_w, const float* __restrict__ sa_w1) {
    int idx = blockIdx.x * blockDim.x + threadIdx.x;
    if (idx < MM*HDIM*INSZ) {
        int m = idx / (HDIM*INSZ), r = idx - m*(HDIM*INSZ);
        int n = r / INSZ, k = r - n*INSZ;
        float x = fc_w[((size_t)m*INSZ + k)*HDIM + n];
        __nv_bfloat16 hi = __float2bfloat16(x);
        g_wt_hi[idx] = hi;
        g_wt_lo[idx] = __float2bfloat16(x - __bfloat162float(hi));
    } else {
        int j = idx - MM*HDIM*INSZ;
        if (j < SAH*HDIM) {
            int n = j / HDIM, k = j - n*HDIM;
            float x = sa_w1[(size_t)k*SAH + n];
            __nv_bfloat16 hi = __float2bfloat16(x);
            g_w1t_hi[j] = hi;
            g_w1t_lo[j] = __float2bfloat16(x - __bfloat162float(hi));
        }
    }
}

// ---- feat = h @ fc_w[m], split-bf16 mma.sync; 2 CTA/SM + cp.async B ----
__global__ __launch_bounds__(256, 2) void k_feat_mma(const float* __restrict__ A,
                                                     const float* __restrict__ AL,
                                                     const float* __restrict__ AR) {
    __shared__ __align__(16) __nv_bfloat16 sAh[128*ASTR], sAl[128*ASTR];
    __shared__ __align__(16) __nv_bfloat16 sBh[128*ASTR], sBl[128*ASTR];
    __shared__ float s_al[128], s_ar[128];
    int tid = threadIdx.x, w = tid >> 5, lane = tid & 31;
    int m = blockIdx.y, row0 = blockIdx.x * 128;
    if (tid < 128) { s_al[tid] = AL[m*HDIM + tid]; s_ar[tid] = AR[m*HDIM + tid]; }
    uint32_t aAh = smem_u32(sAh), aAl = smem_u32(sAl);
    uint32_t aBh = smem_u32(sBh), aBl = smem_u32(sBl);
    float acc[16][4];
#pragma unroll
    for (int j = 0; j < 16; j++)
#pragma unroll
        for (int i = 0; i < 4; i++) acc[j][i] = 0.f;

    const __nv_bfloat16* Bh = g_wt_hi + (size_t)m * HDIM * INSZ;
    const __nv_bfloat16* Bl = g_wt_lo + (size_t)m * HDIM * INSZ;

    for (int kc = 0; kc < 8; kc++) {
        int k0 = kc * 32;
        // B tiles via cp.async: 128 rows x 32 k bf16 hi/lo
#pragma unroll
        for (int i = 0; i < 2; i++) {
            int p = i * 256 + tid;
            int r = p >> 2, q = p & 3;
            uint32_t off = (uint32_t)(r*ASTR + q*8) * 2;
            cp_async16(aBh + off, Bh + (size_t)r * INSZ + k0 + q * 8);
            cp_async16(aBl + off, Bl + (size_t)r * INSZ + k0 + q * 8);
        }
        CP_COMMIT();
        // A: inline fp32 -> hi/lo bf16
#pragma unroll
        for (int i = 0; i < 4; i++) {
            int p = i * 256 + tid;
            int r = p >> 3, q = p & 7;
            int node = row0 + r;
            float4 v = make_float4(0.f, 0.f, 0.f, 0.f);
            if (node < NN) v = *(const float4*)(A + (size_t)node * INSZ + k0 + q * 4);
            cvt_hilo(v, &sAh[r*ASTR + q*4], &sAl[r*ASTR + q*4]);
        }
        CP_WAIT0();
        __syncthreads();
#pragma unroll
        for (int ks = 0; ks < 2; ks++) {
            uint32_t fo = ((lane & 15) * ASTR + ks * 16 + (lane >> 4) * 8) * 2;
            uint32_t ah[4], al[4];
            ldm4(ah, aAh + w * 16 * ASTR * 2 + fo);
            ldm4(al, aAl + w * 16 * ASTR * 2 + fo);
#pragma unroll
            for (int jp = 0; jp < 8; jp++) {
                uint32_t bh[4], bl[4];
                ldm4(bh, aBh + jp * 16 * ASTR * 2 + fo);
                ldm4(bl, aBl + jp * 16 * ASTR * 2 + fo);
                mma16816(acc[2*jp],   ah, bh[0], bh[2]);
                mma16816(acc[2*jp],   ah, bl[0], bl[2]);
                mma16816(acc[2*jp],   al, bh[0], bh[2]);
                mma16816(acc[2*jp+1], ah, bh[1], bh[3]);
                mma16816(acc[2*jp+1], ah, bl[1], bl[3]);
                mma16816(acc[2*jp+1], al, bh[1], bh[3]);
            }
        }
        __syncthreads();
    }
    int g = lane >> 2, t4 = lane & 3;
    int r0 = row0 + w * 16 + g;
    __nv_bfloat16* outp = g_feat16 + (size_t)m * NN * HDIM;
#pragma unroll
    for (int j = 0; j < 16; j++) {
        int col = j * 8 + t4 * 2;
        if (r0 < NN)
            *(__nv_bfloat162*)(outp + (size_t)r0 * HDIM + col) =
                __float22bfloat162_rn(make_float2(acc[j][0], acc[j][1]));
        if (r0 + 8 < NN)
            *(__nv_bfloat162*)(outp + (size_t)(r0 + 8) * HDIM + col) =
                __float22bfloat162_rn(make_float2(acc[j][2], acc[j][3]));
    }
#pragma unroll
    for (int h = 0; h < NH; h++) {
        float pl0 = 0.f, pr0 = 0.f, pl1 = 0.f, pr1 = 0.f;
#pragma unroll
        for (int jj = 2*h; jj <= 2*h+1; jj++) {
            int c0 = jj * 8 + t4 * 2, c1 = c0 + 1;
            float a0 = s_al[c0], a1 = s_al[c1], b0 = s_ar[c0], b1 = s_ar[c1];
            pl0 += acc[jj][0]*a0 + acc[jj][1]*a1;
            pr0 += acc[jj][0]*b0 + acc[jj][1]*b1;
            pl1 += acc[jj][2]*a0 + acc[jj][3]*a1;
            pr1 += acc[jj][2]*b0 + acc[jj][3]*b1;
        }
        pl0 += __shfl_xor_sync(0xffffffffu, pl0, 1); pl0 += __shfl_xor_sync(0xffffffffu, pl0, 2);
        pr0 += __shfl_xor_sync(0xffffffffu, pr0, 1); pr0 += __shfl_xor_sync(0xffffffffu, pr0, 2);
        pl1 += __shfl_xor_sync(0xffffffffu, pl1, 1); pl1 += __shfl_xor_sync(0xffffffffu, pl1, 2);
        pr1 += __shfl_xor_sync(0xffffffffu, pr1, 1); pr1 += __shfl_xor_sync(0xffffffffu, pr1, 2);
        if (t4 == 0) {
            if (r0 < NN) {
                g_el[(m*NN + r0)*NH + h] = pl0;
                g_er[(m*NN + r0)*NH + h] = pr0;
            }
            if (r0 + 8 < NN) {
                g_el[(m*NN + r0 + 8)*NH + h] = pl1;
                g_er[(m*NN + r0 + 8)*NH + h] = pr1;
            }
        }
    }
}

// ---- SA GEMM: A = z hi/lo bf16 via cp.async, fused tanh epilogue ----
__global__ __launch_bounds__(256, 2) void k_sa_mma(const float* __restrict__ B1,
                                                   const float* __restrict__ W2) {
    __shared__ __align__(16) __nv_bfloat16 sAh[128*ASTR], sAl[128*ASTR];
    __shared__ __align__(16) __nv_bfloat16 sBh[128*ASTR], sBl[128*ASTR];
    __shared__ float s_b1[128], s_w2[128];
    int tid = threadIdx.x, w = tid >> 5, lane = tid & 31;
    int row0 = blockIdx.x * 128;
    if (tid < 128) { s_b1[tid] = B1[tid]; s_w2[tid] = W2[tid]; }
    uint32_t aAh = smem_u32(sAh), aAl = smem_u32(sAl);
    uint32_t aBh = smem_u32(sBh), aBl = smem_u32(sBl);
    float acc[16][4];
#pragma unroll
    for (int j = 0; j < 16; j++)
#pragma unroll
        for (int i = 0; i < 4; i++) acc[j][i] = 0.f;

    for (int kc = 0; kc < 4; kc++) {
        int k0 = kc * 32;
        // A: 128 rows x 32 k, hi/lo via cp.async (2 x 16B per thread)
#pragma unroll
        for (int i = 0; i < 2; i++) {
            int p = i * 256 + tid;
            int r = p >> 2, q = p & 3;
            int row = row0 + r;
            uint32_t off = (uint32_t)(r*ASTR + q*8) * 2;
            if (row < SAROWS) {
                cp_async16(aAh + off, g_z_hi + (size_t)row * HDIM + k0 + q * 8);
                cp_async16(aAl + off, g_z_lo + (size_t)row * HDIM + k0 + q * 8);
            } else {
                *(uint4*)&sAh[r*ASTR + q*8] = make_uint4(0,0,0,0);
                *(uint4*)&sAl[r*ASTR + q*8] = make_uint4(0,0,0,0);
            }
        }
#pragma unroll
        for (int i = 0; i < 2; i++) {
            int p = i * 256 + tid;
            int r = p >> 2, q = p & 3;
            uint32_t off = (uint32_t)(r*ASTR + q*8) * 2;
            cp_async16(aBh + off, g_w1t_hi + (size_t)r * HDIM + k0 + q * 8);
            cp_async16(aBl + off, g_w1t_lo + (size_t)r * HDIM + k0 + q * 8);
        }
        CP_COMMIT();
        CP_WAIT0();
        __syncthreads();
#pragma unroll
        for (int ks = 0; ks < 2; ks++) {
            uint32_t fo = ((lane & 15) * ASTR + ks * 16 + (lane >> 4) * 8) * 2;
            uint32_t ah[4], al[4];
            ldm4(ah, aAh + w * 16 * ASTR * 2 + fo);
            ldm4(al, aAl + w * 16 * ASTR * 2 + fo);
#pragma unroll
            for (int jp = 0; jp < 8; jp++) {
                uint32_t bh[4], bl[4];
                ldm4(bh, aBh + jp * 16 * ASTR * 2 + fo);
                ldm4(bl, aBl + jp * 16 * ASTR * 2 + fo);
                mma16816(acc[2*jp],   ah, bh[0], bh[2]);
                mma16816(acc[2*jp],   ah, bl[0], bl[2]);
                mma16816(acc[2*jp],   al, bh[0], bh[2]);
                mma16816(acc[2*jp+1], ah, bh[1], bh[3]);
                mma16816(acc[2*jp+1], ah, bl[1], bl[3]);
                mma16816(acc[2*jp+1], al, bh[1], bh[3]);
            }
        }
        __syncthreads();
    }
    int g = lane >> 2, t4 = lane & 3;
    float s0 = 0.f, s1 = 0.f;
#pragma unroll
    for (int j = 0; j < 16; j++) {
        int col = j * 8 + t4 * 2;
        float b0 = s_b1[col], b1v = s_b1[col + 1];
        float w0 = s_w2[col], w1v = s_w2[col + 1];
        s0 += tanhf(acc[j][0] + b0) * w0 + tanhf(acc[j][1] + b1v) * w1v;
        s1 += tanhf(acc[j][2] + b0) * w0 + tanhf(acc[j][3] + b1v) * w1v;
    }
    s0 += __shfl_xor_sync(0xffffffffu, s0, 1); s0 += __shfl_xor_sync(0xffffffffu, s0, 2);
    s1 += __shfl_xor_sync(0xffffffffu, s1, 1); s1 += __shfl_xor_sync(0xffffffffu, s1, 2);
    if (t4 == 0) {
        int r0 = row0 + w * 16 + g;
        if (r0 < SAROWS)     g_w[r0]     = s0;
        if (r0 + 8 < SAROWS) g_w[r0 + 8] = s1;
    }
}

__global__ void k_hist(const int* __restrict__ edges) {
    int idx = blockIdx.x * blockDim.x + threadIdx.x;
    if (idx >= MM*EE) return;
    int m = idx / EE, e = idx - m*EE;
    atomicAdd(&g_deg[m*NN + edges[(size_t)m*2*EE + EE + e]], 1);
}

__global__ void k_scan() {
    __shared__ int sh[1024];
    int m = blockIdx.x, t = threadIdx.x;
    const int CH = (NN + 1023) / 1024;
    int base = t * CH, sum = 0;
    for (int i = 0; i < CH; i++) { int idx = base+i; if (idx < NN) sum += g_deg[m*NN+idx]; }
    sh[t] = sum; __syncthreads();
    for (int d = 1; d < 1024; d <<= 1) {
        int v = (t >= d) ? sh[t-d] : 0; __syncthreads();
        sh[t] += v; __syncthreads();
    }
    int run = sh[t] - sum;
    for (int i = 0; i < CH; i++) {
        int idx = base+i;
        if (idx < NN) { g_off[m*(NN+1)+idx] = run; g_cur[m*NN+idx] = run; run += g_deg[m*NN+idx]; }
    }
    if (t == 1023) g_off[m*(NN+1)+NN] = sh[1023];
}

__global__ void k_scatter(const int* __restrict__ edges) {
    int idx = blockIdx.x * blockDim.x + threadIdx.x;
    if (idx >= MM*EE) return;
    int m = idx / EE, e = idx - m*EE;
    int src = edges[(size_t)m*2*EE + e];
    int dst = edges[(size_t)m*2*EE + EE + e];
    g_srt[(size_t)m*EE + atomicAdd(&g_cur[m*NN + dst], 1)] = src;
}

// ---- GAT aggregation: warp/dst, bf16 gather, software-pipelined, emits z hi/lo ----
__global__ __launch_bounds__(256) void k_agg() {
    int lane = threadIdx.x & 31;
    int wid  = (blockIdx.x * blockDim.x + threadIdx.x) >> 5;
    int m    = blockIdx.y;
    if (wid >= NN) return;
    int n = wid, h = lane >> 2;
    int beg = g_off[m*(NN+1)+n], end = g_off[m*(NN+1)+n+1];
    float ern = g_er[(m*NN+n)*NH + h];
    const __nv_bfloat16* featm = g_feat16 + (size_t)m*NN*HDIM;
    const float* elm = g_el + m*NN*NH;
    const int*   srcs = g_srt + (size_t)m*EE;
    float den = 0.f, ax = 0.f, ay = 0.f, az = 0.f, aw = 0.f;
    if (beg < end) {
        int s = srcs[beg];
        float el0 = elm[s*NH + h];
        uint2 f = *(const uint2*)(featm + (size_t)s*HDIM + lane*4);
        for (int i = beg + 1; i < end; i++) {
            int s2 = srcs[i];
            float el1 = elm[s2*NH + h];
            uint2 f2 = *(const uint2*)(featm + (size_t)s2*HDIM + lane*4);
            float e = el0 + ern;
            e = (e > 0.f) ? e : 0.2f*e;
            float ex = __expf(e);
            den += ex;
            float2 v0 = __bfloat1622float2(*(__nv_bfloat162*)&f.x);
            float2 v1 = __bfloat1622float2(*(__nv_bfloat162*)&f.y);
            ax += ex*v0.x; ay += ex*v0.y; az += ex*v1.x; aw += ex*v1.y;
            el0 = el1; f = f2;
        }
        float e = el0 + ern;
        e = (e > 0.f) ? e : 0.2f*e;
        float ex = __expf(e);
        den += ex;
        float2 v0 = __bfloat1622float2(*(__nv_bfloat162*)&f.x);
        float2 v1 = __bfloat1622float2(*(__nv_bfloat162*)&f.y);
        ax += ex*v0.x; ay += ex*v0.y; az += ex*v1.x; aw += ex*v1.y;
    }
    float inv = (end > beg) ? 1.f/den : 0.f;
    float r[4]; float v;
    v = ax*inv; r[0] = (v > 0.f) ? v : expm1f(v);
    v = ay*inv; r[1] = (v > 0.f) ? v : expm1f(v);
    v = az*inv; r[2] = (v > 0.f) ? v : expm1f(v);
    v = aw*inv; r[3] = (v > 0.f) ? v : expm1f(v);
    __nv_bfloat16 hv[4], lv[4];
#pragma unroll
    for (int i = 0; i < 4; i++) {
        hv[i] = __float2bfloat16(r[i]);
        lv[i] = __float2bfloat16(r[i] - __bfloat162float(hv[i]));
    }
    size_t zoff = (size_t)(n*MM + m)*HDIM + lane*4;
    *(uint2*)(g_z_hi + zoff) = *(uint2*)hv;
    *(uint2*)(g_z_lo + zoff) = *(uint2*)lv;
}

__global__ void k_wmax() {
    float lm0 = -INFINITY, lm1 = -INFINITY, lm2 = -INFINITY;
    for (int n = blockIdx.x*blockDim.x + threadIdx.x; n < NN; n += gridDim.x*blockDim.x) {
        lm0 = fmaxf(lm0, g_w[n*3+0]); lm1 = fmaxf(lm1, g_w[n*3+1]); lm2 = fmaxf(lm2, g_w[n*3+2]);
    }
#pragma unroll
    for (int off = 16; off > 0; off >>= 1) {
        lm0 = fmaxf(lm0, __shfl_down_sync(0xffffffffu, lm0, off));
        lm1 = fmaxf(lm1, __shfl_down_sync(0xffffffffu, lm1, off));
        lm2 = fmaxf(lm2, __shfl_down_sync(0xffffffffu, lm2, off));
    }
    if ((threadIdx.x & 31) == 0) {
        atomicMaxF(&g_wmax[0], lm0); atomicMaxF(&g_wmax[1], lm1); atomicMaxF(&g_wmax[2], lm2);
    }
}

__global__ void k_sden() {
    float w0 = g_wmax[0], w1 = g_wmax[1], w2 = g_wmax[2];
    float d0 = 0.f, d1 = 0.f, d2 = 0.f;
    for (int n = blockIdx.x*blockDim.x + threadIdx.x; n < NN; n += gridDim.x*blockDim.x) {
        float s0 = __expf(g_w[n*3+0]-w0), s1 = __expf(g_w[n*3+1]-w1), s2 = __expf(g_w[n*3+2]-w2);
        g_s[n*3+0] = s0; g_s[n*3+1] = s1; g_s[n*3+2] = s2;
        d0 += s0; d1 += s1; d2 += s2;
    }
#pragma unroll
    for (int off = 16; off > 0; off >>= 1) {
        d0 += __shfl_down_sync(0xffffffffu, d0, off);
        d1 += __shfl_down_sync(0xffffffffu, d1, off);
        d2 += __shfl_down_sync(0xffffffffu, d2, off);
    }
    if ((threadIdx.x & 31) == 0) {
        atomicAdd(&g_den[0], d0); atomicAdd(&g_den[1], d1); atomicAdd(&g_den[2], d2);
    }
}

__global__ __launch_bounds__(384) void k_fused() {
    int t = threadIdx.x, ms = t >> 7;
    float acc = 0.f;
    for (int n = blockIdx.x; n < NN; n += gridDim.x) {
        size_t idx = (size_t)n*ZROW + t;
        float zv = __bfloat162float(g_z_hi[idx]) + __bfloat162float(g_z_lo[idx]);
        acc += g_s[n*3 + ms] * zv;
    }
    atomicAdd(&g_fus[t], acc);
}

__global__ void k_final(const float* __restrict__ PW, const float* __restrict__ PB,
                        float* __restrict__ out) {
    int t = threadIdx.x;
    if (t >= MM*OUTC) return;
    int m = t / OUTC, o = t - m*OUTC;
    float a = 0.f;
#pragma unroll 8
    for (int c = 0; c < HDIM; c++) a += g_fus[m*HDIM + c] * __ldg(PW + c*OUTC + o);
    out[t] = a / g_den[m] + __ldg(PB + o);
}

extern "C" void kernel_launch(void* const* d_in, const int* in_sizes, int n_in,
                              void* d_out, int out_size) {
    const float* h      = (const float*)d_in[0];
    const int*   edges  = (const int*)d_in[1];
    const float* fc_w   = (const float*)d_in[2];
    const float* attn_l = (const float*)d_in[3];
    const float* attn_r = (const float*)d_in[4];
    const float* sa_w1  = (const float*)d_in[5];
    const float* sa_b1  = (const float*)d_in[6];
    const float* sa_w2  = (const float*)d_in[7];
    const float* pred_w = (const float*)d_in[8];
    const float* pred_b = (const float*)d_in[9];
    float* out = (float*)d_out;

    k_init<<<(MM*NN + 255)/256, 256>>>();
    k_prep<<<(MM*HDIM*INSZ + SAH*HDIM + 255)/256, 256>>>(fc_w, sa_w1);
    k_hist<<<(MM*EE + 255)/256, 256>>>(edges);
    k_feat_mma<<<dim3((NN + 127)/128, MM), 256>>>(h, attn_l, attn_r);
    k_scan<<<MM, 1024>>>();
    k_scatter<<<(MM*EE + 255)/256, 256>>>(edges);
    k_agg<<<dim3((NN + 7)/8, MM), 256>>>();
    k_sa_mma<<<(SAROWS + 127)/128, 256>>>(sa_b1, sa_w2);
    k_wmax<<<64, 256>>>();
    k_sden<<<196, 256>>>();
    k_fused<<<256, 384>>>();
    k_final<<<1, 32>>>(pred_w, pred_b, out);
}

// round 8
// speedup vs baseline: 1.6611x; 1.1083x over previous
#include <cuda_runtime.h>
#include <cuda_bf16.h>
#include <math.h>
#include <stdint.h>

#define NN   50000
#define EE   800000
#define MM   3
#define INSZ 256
#define HDIM 128
#define NH   8
#define DH   16
#define OUTC 8
#define SAH  128
#define ZROW (MM*HDIM)
#define SAROWS (NN*MM)
#define FSTR 36   // fp32 smem row stride (words): bank = 4g+t4+k, conflict-free

__device__ __align__(16) __nv_bfloat16 g_feat16[(size_t)MM*NN*HDIM];
__device__ __align__(16) float g_z[(size_t)SAROWS*HDIM];
__device__ float g_el[MM*NN*NH];
__device__ float g_er[MM*NN*NH];
__device__ int   g_deg[MM*NN];
__device__ int   g_off[MM*(NN+1)];
__device__ int   g_cur[MM*NN];
__device__ int   g_srt[MM*EE];
__device__ float g_w[SAROWS];
__device__ float g_s[SAROWS];
__device__ float g_wmax[MM];
__device__ float g_den[MM];
__device__ float g_fus[MM*HDIM];
__device__ __align__(16) float g_wt[MM*HDIM*INSZ];   // [m][n][k], tf32-rounded
__device__ __align__(16) float g_w1t[SAH*HDIM];      // [n][k], tf32-rounded

__device__ __forceinline__ uint32_t smem_u32(const void* p) {
    uint32_t a;
    asm("{ .reg .u64 t; cvta.to.shared.u64 t, %1; cvt.u32.u64 %0, t; }" : "=r"(a) : "l"(p));
    return a;
}
__device__ __forceinline__ void cp_async16(uint32_t saddr, const void* g) {
    asm volatile("cp.async.cg.shared.global [%0], [%1], 16;" :: "r"(saddr), "l"(g));
}
__device__ __forceinline__ void cp_async16z(uint32_t saddr, const void* g, int sz) {
    asm volatile("cp.async.cg.shared.global [%0], [%1], 16, %2;" :: "r"(saddr), "l"(g), "r"(sz));
}
#define CP_COMMIT() asm volatile("cp.async.commit_group;" ::: "memory")
#define CP_WAIT0()  asm volatile("cp.async.wait_group 0;" ::: "memory")
__device__ __forceinline__ uint32_t tf32r_u(float x) {
    uint32_t u;
    asm("cvt.rna.tf32.f32 %0, %1;" : "=r"(u) : "f"(x));
    return u;
}
__device__ __forceinline__ void mma_tf32(float* c, const uint32_t* a, uint32_t b0, uint32_t b1) {
    asm volatile("mma.sync.aligned.m16n8k8.row.col.f32.tf32.tf32.f32 "
        "{%0,%1,%2,%3}, {%4,%5,%6,%7}, {%8,%9}, {%0,%1,%2,%3};"
        : "+f"(c[0]), "+f"(c[1]), "+f"(c[2]), "+f"(c[3])
        : "r"(a[0]), "r"(a[1]), "r"(a[2]), "r"(a[3]), "r"(b0), "r"(b1));
}
__device__ __forceinline__ void atomicMaxF(float* addr, float v) {
    if (v >= 0.f) atomicMax((int*)addr, __float_as_int(v));
    else          atomicMin((unsigned int*)addr, __float_as_uint(v));
}

__global__ void k_init() {
    int idx = blockIdx.x * blockDim.x + threadIdx.x;
    if (idx < MM*NN) g_deg[idx] = 0;
    if (idx < MM*HDIM) g_fus[idx] = 0.f;
    if (idx < MM) { g_den[idx] = 0.f; g_wmax[idx] = -INFINITY; }
}

__global__ void k_prep(const float* __restrict__ fc_w, const float* __restrict__ sa_w1) {
    int idx = blockIdx.x * blockDim.x + threadIdx.x;
    if (idx < MM*HDIM*INSZ) {
        int m = idx / (HDIM*INSZ), r = idx - m*(HDIM*INSZ);
        int n = r / INSZ, k = r - n*INSZ;
        g_wt[idx] = __uint_as_float(tf32r_u(fc_w[((size_t)m*INSZ + k)*HDIM + n]));
    } else {
        int j = idx - MM*HDIM*INSZ;
        if (j < SAH*HDIM) {
            int n = j / HDIM, k = j - n*HDIM;
            g_w1t[j] = __uint_as_float(tf32r_u(sa_w1[(size_t)k*SAH + n]));
        }
    }
}

// ---- feat = h @ fc_w[m], single-pass tf32 mma; 4Mx2N warps; fused el/er ----
__global__ __launch_bounds__(256, 2) void k_feat_mma(const float* __restrict__ A,
                                                     const float* __restrict__ AL,
                                                     const float* __restrict__ AR) {
    __shared__ __align__(16) float sA[128*FSTR], sB[128*FSTR];
    __shared__ float s_al[128], s_ar[128];
    int tid = threadIdx.x, w = tid >> 5, lane = tid & 31;
    int wm = w >> 1, wn = w & 1, g = lane >> 2, t4 = lane & 3;
    int m = blockIdx.y, row0 = blockIdx.x * 128;
    if (tid < 128) { s_al[tid] = AL[m*HDIM + tid]; s_ar[tid] = AR[m*HDIM + tid]; }
    uint32_t aA = smem_u32(sA), aB = smem_u32(sB);
    float acc[2][8][4];
#pragma unroll
    for (int mt = 0; mt < 2; mt++)
#pragma unroll
        for (int j = 0; j < 8; j++)
#pragma unroll
            for (int i = 0; i < 4; i++) acc[mt][j][i] = 0.f;

    const float* Bm = g_wt + (size_t)m * HDIM * INSZ;

    for (int kc = 0; kc < 8; kc++) {
        int k0 = kc * 32;
#pragma unroll
        for (int i = 0; i < 4; i++) {
            int p = i * 256 + tid;
            int r = p >> 3, q = p & 7;
            int node = row0 + r;
            const float* src = A + (size_t)(node < NN ? node : 0) * INSZ + k0 + q * 4;
            cp_async16z(aA + (uint32_t)(r*FSTR + q*4)*4, src, node < NN ? 16 : 0);
            cp_async16(aB + (uint32_t)(r*FSTR + q*4)*4, Bm + (size_t)r * INSZ + k0 + q * 4);
        }
        CP_COMMIT();
        CP_WAIT0();
        __syncthreads();
#pragma unroll
        for (int ks = 0; ks < 4; ks++) {
            int kb = ks * 8;
            uint32_t af[2][4];
#pragma unroll
            for (int mt = 0; mt < 2; mt++) {
                int ar_ = wm*32 + mt*16 + g;
                af[mt][0] = tf32r_u(sA[ar_*FSTR + kb + t4]);
                af[mt][1] = tf32r_u(sA[(ar_+8)*FSTR + kb + t4]);
                af[mt][2] = tf32r_u(sA[ar_*FSTR + kb + t4 + 4]);
                af[mt][3] = tf32r_u(sA[(ar_+8)*FSTR + kb + t4 + 4]);
            }
#pragma unroll
            for (int jp = 0; jp < 8; jp++) {
                int bn = wn*64 + jp*8 + g;
                uint32_t b0 = __float_as_uint(sB[bn*FSTR + kb + t4]);
                uint32_t b1 = __float_as_uint(sB[bn*FSTR + kb + t4 + 4]);
                mma_tf32(acc[0][jp], af[0], b0, b1);
                mma_tf32(acc[1][jp], af[1], b0, b1);
            }
        }
        __syncthreads();
    }
    __nv_bfloat16* outp = g_feat16 + (size_t)m * NN * HDIM;
#pragma unroll
    for (int mt = 0; mt < 2; mt++) {
        int r0 = row0 + wm*32 + mt*16 + g;
#pragma unroll
        for (int jp = 0; jp < 8; jp++) {
            int col = wn*64 + jp*8 + t4*2;
            if (r0 < NN)
                *(__nv_bfloat162*)(outp + (size_t)r0 * HDIM + col) =
                    __float22bfloat162_rn(make_float2(acc[mt][jp][0], acc[mt][jp][1]));
            if (r0 + 8 < NN)
                *(__nv_bfloat162*)(outp + (size_t)(r0 + 8) * HDIM + col) =
                    __float22bfloat162_rn(make_float2(acc[mt][jp][2], acc[mt][jp][3]));
        }
        // el/er for this warp's 4 heads (global heads wn*4 .. wn*4+3)
#pragma unroll
        for (int hh = 0; hh < 4; hh++) {
            float pl0 = 0.f, pr0 = 0.f, pl1 = 0.f, pr1 = 0.f;
#pragma unroll
            for (int jj = 2*hh; jj <= 2*hh+1; jj++) {
                int c0 = wn*64 + jj*8 + t4*2, c1 = c0 + 1;
                float a0 = s_al[c0], a1 = s_al[c1], b0 = s_ar[c0], b1 = s_ar[c1];
                pl0 += acc[mt][jj][0]*a0 + acc[mt][jj][1]*a1;
                pr0 += acc[mt][jj][0]*b0 + acc[mt][jj][1]*b1;
                pl1 += acc[mt][jj][2]*a0 + acc[mt][jj][3]*a1;
                pr1 += acc[mt][jj][2]*b0 + acc[mt][jj][3]*b1;
            }
            pl0 += __shfl_xor_sync(0xffffffffu, pl0, 1); pl0 += __shfl_xor_sync(0xffffffffu, pl0, 2);
            pr0 += __shfl_xor_sync(0xffffffffu, pr0, 1); pr0 += __shfl_xor_sync(0xffffffffu, pr0, 2);
            pl1 += __shfl_xor_sync(0xffffffffu, pl1, 1); pl1 += __shfl_xor_sync(0xffffffffu, pl1, 2);
            pr1 += __shfl_xor_sync(0xffffffffu, pr1, 1); pr1 += __shfl_xor_sync(0xffffffffu, pr1, 2);
            if (t4 == 0) {
                int h = wn*4 + hh;
                if (r0 < NN) {
                    g_el[(m*NN + r0)*NH + h] = pl0;
                    g_er[(m*NN + r0)*NH + h] = pr0;
                }
                if (r0 + 8 < NN) {
                    g_el[(m*NN + r0 + 8)*NH + h] = pl1;
                    g_er[(m*NN + r0 + 8)*NH + h] = pr1;
                }
            }
        }
    }
}

// ---- SA GEMM tf32 single-pass + fused tanh epilogue (8Mx1N warps) ----
__global__ __launch_bounds__(256, 2) void k_sa_mma(const float* __restrict__ B1,
                                                   const float* __restrict__ W2) {
    __shared__ __align__(16) float sA[128*FSTR], sB[128*FSTR];
    __shared__ float s_b1[128], s_w2[128];
    int tid = threadIdx.x, w = tid >> 5, lane = tid & 31;
    int g = lane >> 2, t4 = lane & 3;
    int row0 = blockIdx.x * 128;
    if (tid < 128) { s_b1[tid] = B1[tid]; s_w2[tid] = W2[tid]; }
    uint32_t aA = smem_u32(sA), aB = smem_u32(sB);
    float acc[16][4];
#pragma unroll
    for (int j = 0; j < 16; j++)
#pragma unroll
        for (int i = 0; i < 4; i++) acc[j][i] = 0.f;

    for (int kc = 0; kc < 4; kc++) {
        int k0 = kc * 32;
#pragma unroll
        for (int i = 0; i < 4; i++) {
            int p = i * 256 + tid;
            int r = p >> 3, q = p & 7;
            int row = row0 + r;
            const float* src = g_z + (size_t)(row < SAROWS ? row : 0) * HDIM + k0 + q * 4;
            cp_async16z(aA + (uint32_t)(r*FSTR + q*4)*4, src, row < SAROWS ? 16 : 0);
            cp_async16(aB + (uint32_t)(r*FSTR + q*4)*4, g_w1t + (size_t)r * HDIM + k0 + q * 4);
        }
        CP_COMMIT();
        CP_WAIT0();
        __syncthreads();
#pragma unroll
        for (int ks = 0; ks < 4; ks++) {
            int kb = ks * 8;
            int ar_ = w*16 + g;
            uint32_t af[4];
            af[0] = tf32r_u(sA[ar_*FSTR + kb + t4]);
            af[1] = tf32r_u(sA[(ar_+8)*FSTR + kb + t4]);
            af[2] = tf32r_u(sA[ar_*FSTR + kb + t4 + 4]);
            af[3] = tf32r_u(sA[(ar_+8)*FSTR + kb + t4 + 4]);
#pragma unroll
            for (int jp = 0; jp < 16; jp++) {
                int bn = jp*8 + g;
                uint32_t b0 = __float_as_uint(sB[bn*FSTR + kb + t4]);
                uint32_t b1 = __float_as_uint(sB[bn*FSTR + kb + t4 + 4]);
                mma_tf32(acc[jp], af, b0, b1);
            }
        }
        __syncthreads();
    }
    float s0 = 0.f, s1 = 0.f;
#pragma unroll
    for (int j = 0; j < 16; j++) {
        int col = j * 8 + t4 * 2;
        float b0 = s_b1[col], b1v = s_b1[col + 1];
        float w0 = s_w2[col], w1v = s_w2[col + 1];
        s0 += tanhf(acc[j][0] + b0) * w0 + tanhf(acc[j][1] + b1v) * w1v;
        s1 += tanhf(acc[j][2] + b0) * w0 + tanhf(acc[j][3] + b1v) * w1v;
    }
    s0 += __shfl_xor_sync(0xffffffffu, s0, 1); s0 += __shfl_xor_sync(0xffffffffu, s0, 2);
    s1 += __shfl_xor_sync(0xffffffffu, s1, 1); s1 += __shfl_xor_sync(0xffffffffu, s1, 2);
    if (t4 == 0) {
        int r0 = row0 + w * 16 + g;
        if (r0 < SAROWS)     g_w[r0]     = s0;
        if (r0 + 8 < SAROWS) g_w[r0 + 8] = s1;
    }
}

__global__ void k_hist(const int* __restrict__ edges) {
    int idx = blockIdx.x * blockDim.x + threadIdx.x;
    if (idx >= MM*EE) return;
    int m = idx / EE, e = idx - m*EE;
    atomicAdd(&g_deg[m*NN + edges[(size_t)m*2*EE + EE + e]], 1);
}

__global__ void k_scan() {
    __shared__ int sh[1024];
    int m = blockIdx.x, t = threadIdx.x;
    const int CH = (NN + 1023) / 1024;
    int base = t * CH, sum = 0;
    for (int i = 0; i < CH; i++) { int idx = base+i; if (idx < NN) sum += g_deg[m*NN+idx]; }
    sh[t] = sum; __syncthreads();
    for (int d = 1; d < 1024; d <<= 1) {
        int v = (t >= d) ? sh[t-d] : 0; __syncthreads();
        sh[t] += v; __syncthreads();
    }
    int run = sh[t] - sum;
    for (int i = 0; i < CH; i++) {
        int idx = base+i;
        if (idx < NN) { g_off[m*(NN+1)+idx] = run; g_cur[m*NN+idx] = run; run += g_deg[m*NN+idx]; }
    }
    if (t == 1023) g_off[m*(NN+1)+NN] = sh[1023];
}

__global__ void k_scatter(const int* __restrict__ edges) {
    int idx = blockIdx.x * blockDim.x + threadIdx.x;
    if (idx >= MM*EE) return;
    int m = idx / EE, e = idx - m*EE;
    int src = edges[(size_t)m*2*EE + e];
    int dst = edges[(size_t)m*2*EE + EE + e];
    g_srt[(size_t)m*EE + atomicAdd(&g_cur[m*NN + dst], 1)] = src;
}

// ---- GAT aggregation: warp/dst, bf16 gather, software-pipelined ----
__global__ __launch_bounds__(256) void k_agg() {
    int lane = threadIdx.x & 31;
    int wid  = (blockIdx.x * blockDim.x + threadIdx.x) >> 5;
    int m    = blockIdx.y;
    if (wid >= NN) return;
    int n = wid, h = lane >> 2;
    int beg = g_off[m*(NN+1)+n], end = g_off[m*(NN+1)+n+1];
    float ern = g_er[(m*NN+n)*NH + h];
    const __nv_bfloat16* featm = g_feat16 + (size_t)m*NN*HDIM;
    const float* elm = g_el + m*NN*NH;
    const int*   srcs = g_srt + (size_t)m*EE;
    float den = 0.f, ax = 0.f, ay = 0.f, az = 0.f, aw = 0.f;
    if (beg < end) {
        int s = srcs[beg];
        float el0 = elm[s*NH + h];
        uint2 f = *(const uint2*)(featm + (size_t)s*HDIM + lane*4);
        for (int i = beg + 1; i < end; i++) {
            int s2 = srcs[i];
            float el1 = elm[s2*NH + h];
            uint2 f2 = *(const uint2*)(featm + (size_t)s2*HDIM + lane*4);
            float e = el0 + ern;
            e = (e > 0.f) ? e : 0.2f*e;
            float ex = __expf(e);
            den += ex;
            float2 v0 = __bfloat1622float2(*(__nv_bfloat162*)&f.x);
            float2 v1 = __bfloat1622float2(*(__nv_bfloat162*)&f.y);
            ax += ex*v0.x; ay += ex*v0.y; az += ex*v1.x; aw += ex*v1.y;
            el0 = el1; f = f2;
        }
        float e = el0 + ern;
        e = (e > 0.f) ? e : 0.2f*e;
        float ex = __expf(e);
        den += ex;
        float2 v0 = __bfloat1622float2(*(__nv_bfloat162*)&f.x);
        float2 v1 = __bfloat1622float2(*(__nv_bfloat162*)&f.y);
        ax += ex*v0.x; ay += ex*v0.y; az += ex*v1.x; aw += ex*v1.y;
    }
    float inv = (end > beg) ? 1.f/den : 0.f;
    float4 o; float v;
    v = ax*inv; o.x = (v > 0.f) ? v : expm1f(v);
    v = ay*inv; o.y = (v > 0.f) ? v : expm1f(v);
    v = az*inv; o.z = (v > 0.f) ? v : expm1f(v);
    v = aw*inv; o.w = (v > 0.f) ? v : expm1f(v);
    *(float4*)(g_z + (size_t)(n*MM + m)*HDIM + lane*4) = o;
}

__global__ void k_wmax() {
    float lm0 = -INFINITY, lm1 = -INFINITY, lm2 = -INFINITY;
    for (int n = blockIdx.x*blockDim.x + threadIdx.x; n < NN; n += gridDim.x*blockDim.x) {
        lm0 = fmaxf(lm0, g_w[n*3+0]); lm1 = fmaxf(lm1, g_w[n*3+1]); lm2 = fmaxf(lm2, g_w[n*3+2]);
    }
#pragma unroll
    for (int off = 16; off > 0; off >>= 1) {
        lm0 = fmaxf(lm0, __shfl_down_sync(0xffffffffu, lm0, off));
        lm1 = fmaxf(lm1, __shfl_down_sync(0xffffffffu, lm1, off));
        lm2 = fmaxf(lm2, __shfl_down_sync(0xffffffffu, lm2, off));
    }
    if ((threadIdx.x & 31) == 0) {
        atomicMaxF(&g_wmax[0], lm0); atomicMaxF(&g_wmax[1], lm1); atomicMaxF(&g_wmax[2], lm2);
    }
}

__global__ void k_sden() {
    float w0 = g_wmax[0], w1 = g_wmax[1], w2 = g_wmax[2];
    float d0 = 0.f, d1 = 0.f, d2 = 0.f;
    for (int n = blockIdx.x*blockDim.x + threadIdx.x; n < NN; n += gridDim.x*blockDim.x) {
        float s0 = __expf(g_w[n*3+0]-w0), s1 = __expf(g_w[n*3+1]-w1), s2 = __expf(g_w[n*3+2]-w2);
        g_s[n*3+0] = s0; g_s[n*3+1] = s1; g_s[n*3+2] = s2;
        d0 += s0; d1 += s1; d2 += s2;
    }
#pragma unroll
    for (int off = 16; off > 0; off >>= 1) {
        d0 += __shfl_down_sync(0xffffffffu, d0, off);
        d1 += __shfl_down_sync(0xffffffffu, d1, off);
        d2 += __shfl_down_sync(0xffffffffu, d2, off);
    }
    if ((threadIdx.x & 31) == 0) {
        atomicAdd(&g_den[0], d0); atomicAdd(&g_den[1], d1); atomicAdd(&g_den[2], d2);
    }
}

__global__ __launch_bounds__(384) void k_fused() {
    int t = threadIdx.x, ms = t >> 7;
    float acc = 0.f;
    for (int n = blockIdx.x; n < NN; n += gridDim.x)
        acc += g_s[n*3 + ms] * g_z[(size_t)n*ZROW + t];
    atomicAdd(&g_fus[t], acc);
}

__global__ void k_final(const float* __restrict__ PW, const float* __restrict__ PB,
                        float* __restrict__ out) {
    int t = threadIdx.x;
    if (t >= MM*OUTC) return;
    int m = t / OUTC, o = t - m*OUTC;
    float a = 0.f;
#pragma unroll 8
    for (int c = 0; c < HDIM; c++) a += g_fus[m*HDIM + c] * __ldg(PW + c*OUTC + o);
    out[t] = a / g_den[m] + __ldg(PB + o);
}

extern "C" void kernel_launch(void* const* d_in, const int* in_sizes, int n_in,
                              void* d_out, int out_size) {
    const float* h      = (const float*)d_in[0];
    const int*   edges  = (const int*)d_in[1];
    const float* fc_w   = (const float*)d_in[2];
    const float* attn_l = (const float*)d_in[3];
    const float* attn_r = (const float*)d_in[4];
    const float* sa_w1  = (const float*)d_in[5];
    const float* sa_b1  = (const float*)d_in[6];
    const float* sa_w2  = (const float*)d_in[7];
    const float* pred_w = (const float*)d_in[8];
    const float* pred_b = (const float*)d_in[9];
    float* out = (float*)d_out;

    k_init<<<(MM*NN + 255)/256, 256>>>();
    k_prep<<<(MM*HDIM*INSZ + SAH*HDIM + 255)/256, 256>>>(fc_w, sa_w1);
    k_hist<<<(MM*EE + 255)/256, 256>>>(edges);
    k_feat_mma<<<dim3((NN + 127)/128, MM), 256>>>(h, attn_l, attn_r);
    k_scan<<<MM, 1024>>>();
    k_scatter<<<(MM*EE + 255)/256, 256>>>(edges);
    k_agg<<<dim3((NN + 7)/8, MM), 256>>>();
    k_sa_mma<<<(SAROWS + 127)/128, 256>>>(sa_b1, sa_w2);
    k_wmax<<<64, 256>>>();
    k_sden<<<196, 256>>>();
    k_fused<<<256, 384>>>();
    k_final<<<1, 32>>>(pred_w, pred_b, out);
}

// round 9
// speedup vs baseline: 1.6845x; 1.0141x over previous
#include <cuda_runtime.h>
#include <cuda_bf16.h>
#include <math.h>
#include <stdint.h>

#define NN   50000
#define EE   800000
#define MM   3
#define INSZ 256
#define HDIM 128
#define NH   8
#define DH   16
#define OUTC 8
#define SAH  128
#define ZROW (MM*HDIM)
#define SAROWS (NN*MM)
#define FSTR 36
#define FEAT_DYN (4*128*FSTR*4)   // 2 bufs x (A+B) x 128 x FSTR floats = 73728 B

__device__ __align__(16) __nv_bfloat16 g_feat16[(size_t)MM*NN*HDIM];
__device__ __align__(16) float g_z[(size_t)SAROWS*HDIM];
__device__ float g_el[MM*NN*NH];
__device__ float g_er[MM*NN*NH];
__device__ int   g_deg[MM*NN];
__device__ int   g_off[MM*(NN+1)];
__device__ int   g_cur[MM*NN];
__device__ int   g_srt[MM*EE];
__device__ float g_w[SAROWS];
__device__ float g_s[SAROWS];
__device__ float g_wmax[MM];
__device__ float g_den[MM];
__device__ float g_fus[MM*HDIM];
__device__ __align__(16) float g_wt[MM*HDIM*INSZ];
__device__ __align__(16) float g_w1t[SAH*HDIM];

__device__ __forceinline__ uint32_t smem_u32(const void* p) {
    uint32_t a;
    asm("{ .reg .u64 t; cvta.to.shared.u64 t, %1; cvt.u32.u64 %0, t; }" : "=r"(a) : "l"(p));
    return a;
}
__device__ __forceinline__ void cp_async16(uint32_t saddr, const void* g) {
    asm volatile("cp.async.cg.shared.global [%0], [%1], 16;" :: "r"(saddr), "l"(g));
}
__device__ __forceinline__ void cp_async16z(uint32_t saddr, const void* g, int sz) {
    asm volatile("cp.async.cg.shared.global [%0], [%1], 16, %2;" :: "r"(saddr), "l"(g), "r"(sz));
}
#define CP_COMMIT() asm volatile("cp.async.commit_group;" ::: "memory")
#define CP_WAIT0()  asm volatile("cp.async.wait_group 0;" ::: "memory")
#define CP_WAIT1()  asm volatile("cp.async.wait_group 1;" ::: "memory")
__device__ __forceinline__ uint32_t tf32r_u(float x) {
    uint32_t u;
    asm("cvt.rna.tf32.f32 %0, %1;" : "=r"(u) : "f"(x));
    return u;
}
__device__ __forceinline__ void mma_tf32(float* c, const uint32_t* a, uint32_t b0, uint32_t b1) {
    asm volatile("mma.sync.aligned.m16n8k8.row.col.f32.tf32.tf32.f32 "
        "{%0,%1,%2,%3}, {%4,%5,%6,%7}, {%8,%9}, {%0,%1,%2,%3};"
        : "+f"(c[0]), "+f"(c[1]), "+f"(c[2]), "+f"(c[3])
        : "r"(a[0]), "r"(a[1]), "r"(a[2]), "r"(a[3]), "r"(b0), "r"(b1));
}
__device__ __forceinline__ void atomicMaxF(float* addr, float v) {
    if (v >= 0.f) atomicMax((int*)addr, __float_as_int(v));
    else          atomicMin((unsigned int*)addr, __float_as_uint(v));
}

__global__ void k_init() {
    int idx = blockIdx.x * blockDim.x + threadIdx.x;
    if (idx < MM*NN) g_deg[idx] = 0;
    if (idx < MM*HDIM) g_fus[idx] = 0.f;
    if (idx < MM) { g_den[idx] = 0.f; g_wmax[idx] = -INFINITY; }
}

__global__ void k_prep(const float* __restrict__ fc_w, const float* __restrict__ sa_w1) {
    int idx = blockIdx.x * blockDim.x + threadIdx.x;
    if (idx < MM*HDIM*INSZ) {
        int m = idx / (HDIM*INSZ), r = idx - m*(HDIM*INSZ);
        int n = r / INSZ, k = r - n*INSZ;
        g_wt[idx] = __uint_as_float(tf32r_u(fc_w[((size_t)m*INSZ + k)*HDIM + n]));
    } else {
        int j = idx - MM*HDIM*INSZ;
        if (j < SAH*HDIM) {
            int n = j / HDIM, k = j - n*HDIM;
            g_w1t[j] = __uint_as_float(tf32r_u(sa_w1[(size_t)k*SAH + n]));
        }
    }
}

// ---- feat = h @ fc_w[m], tf32 mma, double-buffered cp.async pipeline ----
__global__ __launch_bounds__(256, 2) void k_feat_mma(const float* __restrict__ A,
                                                     const float* __restrict__ AL,
                                                     const float* __restrict__ AR) {
    extern __shared__ __align__(16) float smf[];
    float* sA = smf;                    // 2 x 128*FSTR
    float* sB = smf + 2*128*FSTR;       // 2 x 128*FSTR
    __shared__ float s_al[128], s_ar[128];
    int tid = threadIdx.x, w = tid >> 5, lane = tid & 31;
    int wm = w >> 1, wn = w & 1, g = lane >> 2, t4 = lane & 3;
    int m = blockIdx.y, row0 = blockIdx.x * 128;
    if (tid < 128) { s_al[tid] = AL[m*HDIM + tid]; s_ar[tid] = AR[m*HDIM + tid]; }
    float acc[2][8][4];
#pragma unroll
    for (int mt = 0; mt < 2; mt++)
#pragma unroll
        for (int j = 0; j < 8; j++)
#pragma unroll
            for (int i = 0; i < 4; i++) acc[mt][j][i] = 0.f;

    const float* Bm = g_wt + (size_t)m * HDIM * INSZ;
    int r_ld = tid >> 3, q_ld = tid & 7;   // per-thread load coords (4 iters of 256)

    // stage(kc, buf)
    auto stage = [&](int kc, int buf) {
        int k0 = kc * 32;
        uint32_t aA = smem_u32(sA + buf*128*FSTR);
        uint32_t aB = smem_u32(sB + buf*128*FSTR);
#pragma unroll
        for (int i = 0; i < 4; i++) {
            int r = r_ld + i*32, q = q_ld;
            int node = row0 + r;
            const float* src = A + (size_t)(node < NN ? node : 0) * INSZ + k0 + q * 4;
            cp_async16z(aA + (uint32_t)(r*FSTR + q*4)*4, src, node < NN ? 16 : 0);
            cp_async16(aB + (uint32_t)(r*FSTR + q*4)*4, Bm + (size_t)r * INSZ + k0 + q * 4);
        }
        CP_COMMIT();
    };

    stage(0, 0);
    for (int kc = 0; kc < 8; kc++) {
        if (kc < 7) { stage(kc + 1, (kc + 1) & 1); CP_WAIT1(); }
        else        { CP_WAIT0(); }
        __syncthreads();
        const float* sAb = sA + (kc & 1)*128*FSTR;
        const float* sBb = sB + (kc & 1)*128*FSTR;
#pragma unroll
        for (int ks = 0; ks < 4; ks++) {
            int kb = ks * 8;
            uint32_t af[2][4];
#pragma unroll
            for (int mt = 0; mt < 2; mt++) {
                int ar_ = wm*32 + mt*16 + g;
                af[mt][0] = tf32r_u(sAb[ar_*FSTR + kb + t4]);
                af[mt][1] = tf32r_u(sAb[(ar_+8)*FSTR + kb + t4]);
                af[mt][2] = tf32r_u(sAb[ar_*FSTR + kb + t4 + 4]);
                af[mt][3] = tf32r_u(sAb[(ar_+8)*FSTR + kb + t4 + 4]);
            }
#pragma unroll
            for (int jp = 0; jp < 8; jp++) {
                int bn = wn*64 + jp*8 + g;
                uint32_t b0 = __float_as_uint(sBb[bn*FSTR + kb + t4]);
                uint32_t b1 = __float_as_uint(sBb[bn*FSTR + kb + t4 + 4]);
                mma_tf32(acc[0][jp], af[0], b0, b1);
                mma_tf32(acc[1][jp], af[1], b0, b1);
            }
        }
        __syncthreads();
    }
    __nv_bfloat16* outp = g_feat16 + (size_t)m * NN * HDIM;
#pragma unroll
    for (int mt = 0; mt < 2; mt++) {
        int r0 = row0 + wm*32 + mt*16 + g;
#pragma unroll
        for (int jp = 0; jp < 8; jp++) {
            int col = wn*64 + jp*8 + t4*2;
            if (r0 < NN)
                *(__nv_bfloat162*)(outp + (size_t)r0 * HDIM + col) =
                    __float22bfloat162_rn(make_float2(acc[mt][jp][0], acc[mt][jp][1]));
            if (r0 + 8 < NN)
                *(__nv_bfloat162*)(outp + (size_t)(r0 + 8) * HDIM + col) =
                    __float22bfloat162_rn(make_float2(acc[mt][jp][2], acc[mt][jp][3]));
        }
#pragma unroll
        for (int hh = 0; hh < 4; hh++) {
            float pl0 = 0.f, pr0 = 0.f, pl1 = 0.f, pr1 = 0.f;
#pragma unroll
            for (int jj = 2*hh; jj <= 2*hh+1; jj++) {
                int c0 = wn*64 + jj*8 + t4*2, c1 = c0 + 1;
                float a0 = s_al[c0], a1 = s_al[c1], b0 = s_ar[c0], b1 = s_ar[c1];
                pl0 += acc[mt][jj][0]*a0 + acc[mt][jj][1]*a1;
                pr0 += acc[mt][jj][0]*b0 + acc[mt][jj][1]*b1;
                pl1 += acc[mt][jj][2]*a0 + acc[mt][jj][3]*a1;
                pr1 += acc[mt][jj][2]*b0 + acc[mt][jj][3]*b1;
            }
            pl0 += __shfl_xor_sync(0xffffffffu, pl0, 1); pl0 += __shfl_xor_sync(0xffffffffu, pl0, 2);
            pr0 += __shfl_xor_sync(0xffffffffu, pr0, 1); pr0 += __shfl_xor_sync(0xffffffffu, pr0, 2);
            pl1 += __shfl_xor_sync(0xffffffffu, pl1, 1); pl1 += __shfl_xor_sync(0xffffffffu, pl1, 2);
            pr1 += __shfl_xor_sync(0xffffffffu, pr1, 1); pr1 += __shfl_xor_sync(0xffffffffu, pr1, 2);
            if (t4 == 0) {
                int h = wn*4 + hh;
                if (r0 < NN) {
                    g_el[(m*NN + r0)*NH + h] = pl0;
                    g_er[(m*NN + r0)*NH + h] = pr0;
                }
                if (r0 + 8 < NN) {
                    g_el[(m*NN + r0 + 8)*NH + h] = pl1;
                    g_er[(m*NN + r0 + 8)*NH + h] = pr1;
                }
            }
        }
    }
}

// ---- SA GEMM tf32 + fused tanh epilogue ----
__global__ __launch_bounds__(256, 2) void k_sa_mma(const float* __restrict__ B1,
                                                   const float* __restrict__ W2) {
    __shared__ __align__(16) float sA[128*FSTR], sB[128*FSTR];
    __shared__ float s_b1[128], s_w2[128];
    int tid = threadIdx.x, w = tid >> 5, lane = tid & 31;
    int g = lane >> 2, t4 = lane & 3;
    int row0 = blockIdx.x * 128;
    if (tid < 128) { s_b1[tid] = B1[tid]; s_w2[tid] = W2[tid]; }
    uint32_t aA = smem_u32(sA), aB = smem_u32(sB);
    float acc[16][4];
#pragma unroll
    for (int j = 0; j < 16; j++)
#pragma unroll
        for (int i = 0; i < 4; i++) acc[j][i] = 0.f;

    for (int kc = 0; kc < 4; kc++) {
        int k0 = kc * 32;
#pragma unroll
        for (int i = 0; i < 4; i++) {
            int p = i * 256 + tid;
            int r = p >> 3, q = p & 7;
            int row = row0 + r;
            const float* src = g_z + (size_t)(row < SAROWS ? row : 0) * HDIM + k0 + q * 4;
            cp_async16z(aA + (uint32_t)(r*FSTR + q*4)*4, src, row < SAROWS ? 16 : 0);
            cp_async16(aB + (uint32_t)(r*FSTR + q*4)*4, g_w1t + (size_t)r * HDIM + k0 + q * 4);
        }
        CP_COMMIT();
        CP_WAIT0();
        __syncthreads();
#pragma unroll
        for (int ks = 0; ks < 4; ks++) {
            int kb = ks * 8;
            int ar_ = w*16 + g;
            uint32_t af[4];
            af[0] = tf32r_u(sA[ar_*FSTR + kb + t4]);
            af[1] = tf32r_u(sA[(ar_+8)*FSTR + kb + t4]);
            af[2] = tf32r_u(sA[ar_*FSTR + kb + t4 + 4]);
            af[3] = tf32r_u(sA[(ar_+8)*FSTR + kb + t4 + 4]);
#pragma unroll
            for (int jp = 0; jp < 16; jp++) {
                int bn = jp*8 + g;
                uint32_t b0 = __float_as_uint(sB[bn*FSTR + kb + t4]);
                uint32_t b1 = __float_as_uint(sB[bn*FSTR + kb + t4 + 4]);
                mma_tf32(acc[jp], af, b0, b1);
            }
        }
        __syncthreads();
    }
    float s0 = 0.f, s1 = 0.f;
#pragma unroll
    for (int j = 0; j < 16; j++) {
        int col = j * 8 + t4 * 2;
        float b0 = s_b1[col], b1v = s_b1[col + 1];
        float w0 = s_w2[col], w1v = s_w2[col + 1];
        s0 += tanhf(acc[j][0] + b0) * w0 + tanhf(acc[j][1] + b1v) * w1v;
        s1 += tanhf(acc[j][2] + b0) * w0 + tanhf(acc[j][3] + b1v) * w1v;
    }
    s0 += __shfl_xor_sync(0xffffffffu, s0, 1); s0 += __shfl_xor_sync(0xffffffffu, s0, 2);
    s1 += __shfl_xor_sync(0xffffffffu, s1, 1); s1 += __shfl_xor_sync(0xffffffffu, s1, 2);
    if (t4 == 0) {
        int r0 = row0 + w * 16 + g;
        if (r0 < SAROWS)     g_w[r0]     = s0;
        if (r0 + 8 < SAROWS) g_w[r0 + 8] = s1;
    }
}

__global__ void k_hist(const int* __restrict__ edges) {
    int idx = blockIdx.x * blockDim.x + threadIdx.x;
    if (idx >= MM*EE) return;
    int m = idx / EE, e = idx - m*EE;
    atomicAdd(&g_deg[m*NN + edges[(size_t)m*2*EE + EE + e]], 1);
}

__global__ void k_scan() {
    __shared__ int sh[1024];
    int m = blockIdx.x, t = threadIdx.x;
    const int CH = (NN + 1023) / 1024;
    int base = t * CH, sum = 0;
    for (int i = 0; i < CH; i++) { int idx = base+i; if (idx < NN) sum += g_deg[m*NN+idx]; }
    sh[t] = sum; __syncthreads();
    for (int d = 1; d < 1024; d <<= 1) {
        int v = (t >= d) ? sh[t-d] : 0; __syncthreads();
        sh[t] += v; __syncthreads();
    }
    int run = sh[t] - sum;
    for (int i = 0; i < CH; i++) {
        int idx = base+i;
        if (idx < NN) { g_off[m*(NN+1)+idx] = run; g_cur[m*NN+idx] = run; run += g_deg[m*NN+idx]; }
    }
    if (t == 1023) g_off[m*(NN+1)+NN] = sh[1023];
}

__global__ void k_scatter(const int* __restrict__ edges) {
    int idx = blockIdx.x * blockDim.x + threadIdx.x;
    if (idx >= MM*EE) return;
    int m = idx / EE, e = idx - m*EE;
    int src = edges[(size_t)m*2*EE + e];
    int dst = edges[(size_t)m*2*EE + EE + e];
    g_srt[(size_t)m*EE + atomicAdd(&g_cur[m*NN + dst], 1)] = src;
}

// ---- GAT aggregation: warp/dst, bf16 gather, unroll-2 (MLP x2) ----
__global__ __launch_bounds__(256) void k_agg() {
    int lane = threadIdx.x & 31;
    int wid  = (blockIdx.x * blockDim.x + threadIdx.x) >> 5;
    int m    = blockIdx.y;
    if (wid >= NN) return;
    int n = wid, h = lane >> 2;
    int beg = g_off[m*(NN+1)+n], end = g_off[m*(NN+1)+n+1];
    float ern = g_er[(m*NN+n)*NH + h];
    const __nv_bfloat16* featm = g_feat16 + (size_t)m*NN*HDIM;
    const float* elm = g_el + m*NN*NH;
    const int*   srcs = g_srt + (size_t)m*EE;
    float den = 0.f, ax = 0.f, ay = 0.f, az = 0.f, aw = 0.f;
    float dn2 = 0.f, bx = 0.f, by = 0.f, bz = 0.f, bw = 0.f;
    int i = beg;
    for (; i + 2 <= end; i += 2) {
        int s0 = __ldg(srcs + i), s1 = __ldg(srcs + i + 1);
        float e0 = __ldg(elm + s0*NH + h) + ern;
        float e1 = __ldg(elm + s1*NH + h) + ern;
        uint2 f0 = *(const uint2*)(featm + (size_t)s0*HDIM + lane*4);
        uint2 f1 = *(const uint2*)(featm + (size_t)s1*HDIM + lane*4);
        e0 = (e0 > 0.f) ? e0 : 0.2f*e0;
        e1 = (e1 > 0.f) ? e1 : 0.2f*e1;
        float x0 = __expf(e0), x1 = __expf(e1);
        den += x0; dn2 += x1;
        float2 u0 = __bfloat1622float2(*(__nv_bfloat162*)&f0.x);
        float2 u1 = __bfloat1622float2(*(__nv_bfloat162*)&f0.y);
        float2 v0 = __bfloat1622float2(*(__nv_bfloat162*)&f1.x);
        float2 v1 = __bfloat1622float2(*(__nv_bfloat162*)&f1.y);
        ax += x0*u0.x; ay += x0*u0.y; az += x0*u1.x; aw += x0*u1.y;
        bx += x1*v0.x; by += x1*v0.y; bz += x1*v1.x; bw += x1*v1.y;
    }
    if (i < end) {
        int s0 = __ldg(srcs + i);
        float e0 = __ldg(elm + s0*NH + h) + ern;
        uint2 f0 = *(const uint2*)(featm + (size_t)s0*HDIM + lane*4);
        e0 = (e0 > 0.f) ? e0 : 0.2f*e0;
        float x0 = __expf(e0);
        den += x0;
        float2 u0 = __bfloat1622float2(*(__nv_bfloat162*)&f0.x);
        float2 u1 = __bfloat1622float2(*(__nv_bfloat162*)&f0.y);
        ax += x0*u0.x; ay += x0*u0.y; az += x0*u1.x; aw += x0*u1.y;
    }
    den += dn2; ax += bx; ay += by; az += bz; aw += bw;
    float inv = (end > beg) ? 1.f/den : 0.f;
    float4 o; float v;
    v = ax*inv; o.x = (v > 0.f) ? v : expm1f(v);
    v = ay*inv; o.y = (v > 0.f) ? v : expm1f(v);
    v = az*inv; o.z = (v > 0.f) ? v : expm1f(v);
    v = aw*inv; o.w = (v > 0.f) ? v : expm1f(v);
    *(float4*)(g_z + (size_t)(n*MM + m)*HDIM + lane*4) = o;
}

__global__ void k_wmax() {
    float lm0 = -INFINITY, lm1 = -INFINITY, lm2 = -INFINITY;
    for (int n = blockIdx.x*blockDim.x + threadIdx.x; n < NN; n += gridDim.x*blockDim.x) {
        lm0 = fmaxf(lm0, g_w[n*3+0]); lm1 = fmaxf(lm1, g_w[n*3+1]); lm2 = fmaxf(lm2, g_w[n*3+2]);
    }
#pragma unroll
    for (int off = 16; off > 0; off >>= 1) {
        lm0 = fmaxf(lm0, __shfl_down_sync(0xffffffffu, lm0, off));
        lm1 = fmaxf(lm1, __shfl_down_sync(0xffffffffu, lm1, off));
        lm2 = fmaxf(lm2, __shfl_down_sync(0xffffffffu, lm2, off));
    }
    if ((threadIdx.x & 31) == 0) {
        atomicMaxF(&g_wmax[0], lm0); atomicMaxF(&g_wmax[1], lm1); atomicMaxF(&g_wmax[2], lm2);
    }
}

__global__ void k_sden() {
    float w0 = g_wmax[0], w1 = g_wmax[1], w2 = g_wmax[2];
    float d0 = 0.f, d1 = 0.f, d2 = 0.f;
    for (int n = blockIdx.x*blockDim.x + threadIdx.x; n < NN; n += gridDim.x*blockDim.x) {
        float s0 = __expf(g_w[n*3+0]-w0), s1 = __expf(g_w[n*3+1]-w1), s2 = __expf(g_w[n*3+2]-w2);
        g_s[n*3+0] = s0; g_s[n*3+1] = s1; g_s[n*3+2] = s2;
        d0 += s0; d1 += s1; d2 += s2;
    }
#pragma unroll
    for (int off = 16; off > 0; off >>= 1) {
        d0 += __shfl_down_sync(0xffffffffu, d0, off);
        d1 += __shfl_down_sync(0xffffffffu, d1, off);
        d2 += __shfl_down_sync(0xffffffffu, d2, off);
    }
    if ((threadIdx.x & 31) == 0) {
        atomicAdd(&g_den[0], d0); atomicAdd(&g_den[1], d1); atomicAdd(&g_den[2], d2);
    }
}

__global__ __launch_bounds__(384) void k_fused() {
    int t = threadIdx.x, ms = t >> 7;
    float acc = 0.f;
    for (int n = blockIdx.x; n < NN; n += gridDim.x)
        acc += g_s[n*3 + ms] * g_z[(size_t)n*ZROW + t];
    atomicAdd(&g_fus[t], acc);
}

__global__ void k_final(const float* __restrict__ PW, const float* __restrict__ PB,
                        float* __restrict__ out) {
    int t = threadIdx.x;
    if (t >= MM*OUTC) return;
    int m = t / OUTC, o = t - m*OUTC;
    float a = 0.f;
#pragma unroll 8
    for (int c = 0; c < HDIM; c++) a += g_fus[m*HDIM + c] * __ldg(PW + c*OUTC + o);
    out[t] = a / g_den[m] + __ldg(PB + o);
}

extern "C" void kernel_launch(void* const* d_in, const int* in_sizes, int n_in,
                              void* d_out, int out_size) {
    const float* h      = (const float*)d_in[0];
    const int*   edges  = (const int*)d_in[1];
    const float* fc_w   = (const float*)d_in[2];
    const float* attn_l = (const float*)d_in[3];
    const float* attn_r = (const float*)d_in[4];
    const float* sa_w1  = (const float*)d_in[5];
    const float* sa_b1  = (const float*)d_in[6];
    const float* sa_w2  = (const float*)d_in[7];
    const float* pred_w = (const float*)d_in[8];
    const float* pred_b = (const float*)d_in[9];
    float* out = (float*)d_out;

    static int attr_done = 0;
    if (!attr_done) {
        cudaFuncSetAttribute(k_feat_mma, cudaFuncAttributeMaxDynamicSharedMemorySize, FEAT_DYN);
        attr_done = 1;
    }

    k_init<<<(MM*NN + 255)/256, 256>>>();
    k_prep<<<(MM*HDIM*INSZ + SAH*HDIM + 255)/256, 256>>>(fc_w, sa_w1);
    k_hist<<<(MM*EE + 255)/256, 256>>>(edges);
    k_feat_mma<<<dim3((NN + 127)/128, MM), 256, FEAT_DYN>>>(h, attn_l, attn_r);
    k_scan<<<MM, 1024>>>();
    k_scatter<<<(MM*EE + 255)/256, 256>>>(edges);
    k_agg<<<dim3((NN + 7)/8, MM), 256>>>();
    k_sa_mma<<<(SAROWS + 127)/128, 256>>>(sa_b1, sa_w2);
    k_wmax<<<64, 256>>>();
    k_sden<<<196, 256>>>();
    k_fused<<<256, 384>>>();
    k_final<<<1, 32>>>(pred_w, pred_b, out);
}

// round 10
// speedup vs baseline: 1.9611x; 1.1642x over previous
#include <cuda_runtime.h>
#include <cuda_bf16.h>
#include <math.h>
#include <stdint.h>

#define NN   50000
#define EE   800000
#define MM   3
#define INSZ 256
#define HDIM 128
#define NH   8
#define DH   16
#define OUTC 8
#define SAH  128
#define ZROW (MM*HDIM)
#define SAROWS (NN*MM)
#define FSTR 36
#define FEAT_DYN (4*128*FSTR*4)

__device__ __align__(16) __nv_bfloat16 g_feat16[(size_t)MM*NN*HDIM];
__device__ __align__(16) float g_z[(size_t)SAROWS*HDIM];
__device__ float g_el[MM*NN*NH];
__device__ float g_er[MM*NN*NH];
__device__ int   g_deg[MM*NN];
__device__ int   g_off[MM*(NN+1)];
__device__ int   g_cur[MM*NN];
__device__ int   g_srt[MM*EE];
__device__ float g_w[SAROWS];
__device__ float g_s[SAROWS];
__device__ float g_wmax[MM];
__device__ float g_den[MM];
__device__ float g_fus[MM*HDIM];
__device__ __align__(16) float g_wt[MM*HDIM*INSZ];
__device__ __align__(16) float g_w1t[SAH*HDIM];

__device__ __forceinline__ uint32_t smem_u32(const void* p) {
    uint32_t a;
    asm("{ .reg .u64 t; cvta.to.shared.u64 t, %1; cvt.u32.u64 %0, t; }" : "=r"(a) : "l"(p));
    return a;
}
__device__ __forceinline__ void cp_async16(uint32_t saddr, const void* g) {
    asm volatile("cp.async.cg.shared.global [%0], [%1], 16;" :: "r"(saddr), "l"(g));
}
__device__ __forceinline__ void cp_async16z(uint32_t saddr, const void* g, int sz) {
    asm volatile("cp.async.cg.shared.global [%0], [%1], 16, %2;" :: "r"(saddr), "l"(g), "r"(sz));
}
#define CP_COMMIT() asm volatile("cp.async.commit_group;" ::: "memory")
#define CP_WAIT0()  asm volatile("cp.async.wait_group 0;" ::: "memory")
#define CP_WAIT1()  asm volatile("cp.async.wait_group 1;" ::: "memory")
__device__ __forceinline__ uint32_t tf32r_u(float x) {
    uint32_t u;
    asm("cvt.rna.tf32.f32 %0, %1;" : "=r"(u) : "f"(x));
    return u;
}
__device__ __forceinline__ void mma_tf32(float* c, const uint32_t* a, uint32_t b0, uint32_t b1) {
    asm volatile("mma.sync.aligned.m16n8k8.row.col.f32.tf32.tf32.f32 "
        "{%0,%1,%2,%3}, {%4,%5,%6,%7}, {%8,%9}, {%0,%1,%2,%3};"
        : "+f"(c[0]), "+f"(c[1]), "+f"(c[2]), "+f"(c[3])
        : "r"(a[0]), "r"(a[1]), "r"(a[2]), "r"(a[3]), "r"(b0), "r"(b1));
}
__device__ __forceinline__ void atomicMaxF(float* addr, float v) {
    if (v >= 0.f) atomicMax((int*)addr, __float_as_int(v));
    else          atomicMin((unsigned int*)addr, __float_as_uint(v));
}

__global__ void k_init() {
    int idx = blockIdx.x * blockDim.x + threadIdx.x;
    if (idx < MM*NN) g_deg[idx] = 0;
    if (idx < MM*HDIM) g_fus[idx] = 0.f;
    if (idx < MM) { g_den[idx] = 0.f; g_wmax[idx] = -INFINITY; }
}

__global__ void k_prep(const float* __restrict__ fc_w, const float* __restrict__ sa_w1) {
    int idx = blockIdx.x * blockDim.x + threadIdx.x;
    if (idx < MM*HDIM*INSZ) {
        int m = idx / (HDIM*INSZ), r = idx - m*(HDIM*INSZ);
        int n = r / INSZ, k = r - n*INSZ;
        g_wt[idx] = __uint_as_float(tf32r_u(fc_w[((size_t)m*INSZ + k)*HDIM + n]));
    } else {
        int j = idx - MM*HDIM*INSZ;
        if (j < SAH*HDIM) {
            int n = j / HDIM, k = j - n*HDIM;
            g_w1t[j] = __uint_as_float(tf32r_u(sa_w1[(size_t)k*SAH + n]));
        }
    }
}

// ---- feat = h @ fc_w[m], tf32 mma, double-buffered cp.async pipeline ----
__global__ __launch_bounds__(256, 2) void k_feat_mma(const float* __restrict__ A,
                                                     const float* __restrict__ AL,
                                                     const float* __restrict__ AR) {
    extern __shared__ __align__(16) float smf[];
    float* sA = smf;
    float* sB = smf + 2*128*FSTR;
    __shared__ float s_al[128], s_ar[128];
    int tid = threadIdx.x, w = tid >> 5, lane = tid & 31;
    int wm = w >> 1, wn = w & 1, g = lane >> 2, t4 = lane & 3;
    int m = blockIdx.y, row0 = blockIdx.x * 128;
    if (tid < 128) { s_al[tid] = AL[m*HDIM + tid]; s_ar[tid] = AR[m*HDIM + tid]; }
    float acc[2][8][4];
#pragma unroll
    for (int mt = 0; mt < 2; mt++)
#pragma unroll
        for (int j = 0; j < 8; j++)
#pragma unroll
            for (int i = 0; i < 4; i++) acc[mt][j][i] = 0.f;

    const float* Bm = g_wt + (size_t)m * HDIM * INSZ;
    int r_ld = tid >> 3, q_ld = tid & 7;

    auto stage = [&](int kc, int buf) {
        int k0 = kc * 32;
        uint32_t aA = smem_u32(sA + buf*128*FSTR);
        uint32_t aB = smem_u32(sB + buf*128*FSTR);
#pragma unroll
        for (int i = 0; i < 4; i++) {
            int r = r_ld + i*32, q = q_ld;
            int node = row0 + r;
            const float* src = A + (size_t)(node < NN ? node : 0) * INSZ + k0 + q * 4;
            cp_async16z(aA + (uint32_t)(r*FSTR + q*4)*4, src, node < NN ? 16 : 0);
            cp_async16(aB + (uint32_t)(r*FSTR + q*4)*4, Bm + (size_t)r * INSZ + k0 + q * 4);
        }
        CP_COMMIT();
    };

    stage(0, 0);
    for (int kc = 0; kc < 8; kc++) {
        if (kc < 7) { stage(kc + 1, (kc + 1) & 1); CP_WAIT1(); }
        else        { CP_WAIT0(); }
        __syncthreads();
        const float* sAb = sA + (kc & 1)*128*FSTR;
        const float* sBb = sB + (kc & 1)*128*FSTR;
#pragma unroll
        for (int ks = 0; ks < 4; ks++) {
            int kb = ks * 8;
            uint32_t af[2][4];
#pragma unroll
            for (int mt = 0; mt < 2; mt++) {
                int ar_ = wm*32 + mt*16 + g;
                af[mt][0] = tf32r_u(sAb[ar_*FSTR + kb + t4]);
                af[mt][1] = tf32r_u(sAb[(ar_+8)*FSTR + kb + t4]);
                af[mt][2] = tf32r_u(sAb[ar_*FSTR + kb + t4 + 4]);
                af[mt][3] = tf32r_u(sAb[(ar_+8)*FSTR + kb + t4 + 4]);
            }
#pragma unroll
            for (int jp = 0; jp < 8; jp++) {
                int bn = wn*64 + jp*8 + g;
                uint32_t b0 = __float_as_uint(sBb[bn*FSTR + kb + t4]);
                uint32_t b1 = __float_as_uint(sBb[bn*FSTR + kb + t4 + 4]);
                mma_tf32(acc[0][jp], af[0], b0, b1);
                mma_tf32(acc[1][jp], af[1], b0, b1);
            }
        }
        __syncthreads();
    }
    __nv_bfloat16* outp = g_feat16 + (size_t)m * NN * HDIM;
#pragma unroll
    for (int mt = 0; mt < 2; mt++) {
        int r0 = row0 + wm*32 + mt*16 + g;
#pragma unroll
        for (int jp = 0; jp < 8; jp++) {
            int col = wn*64 + jp*8 + t4*2;
            if (r0 < NN)
                *(__nv_bfloat162*)(outp + (size_t)r0 * HDIM + col) =
                    __float22bfloat162_rn(make_float2(acc[mt][jp][0], acc[mt][jp][1]));
            if (r0 + 8 < NN)
                *(__nv_bfloat162*)(outp + (size_t)(r0 + 8) * HDIM + col) =
                    __float22bfloat162_rn(make_float2(acc[mt][jp][2], acc[mt][jp][3]));
        }
#pragma unroll
        for (int hh = 0; hh < 4; hh++) {
            float pl0 = 0.f, pr0 = 0.f, pl1 = 0.f, pr1 = 0.f;
#pragma unroll
            for (int jj = 2*hh; jj <= 2*hh+1; jj++) {
                int c0 = wn*64 + jj*8 + t4*2, c1 = c0 + 1;
                float a0 = s_al[c0], a1 = s_al[c1], b0 = s_ar[c0], b1 = s_ar[c1];
                pl0 += acc[mt][jj][0]*a0 + acc[mt][jj][1]*a1;
                pr0 += acc[mt][jj][0]*b0 + acc[mt][jj][1]*b1;
                pl1 += acc[mt][jj][2]*a0 + acc[mt][jj][3]*a1;
                pr1 += acc[mt][jj][2]*b0 + acc[mt][jj][3]*b1;
            }
            pl0 += __shfl_xor_sync(0xffffffffu, pl0, 1); pl0 += __shfl_xor_sync(0xffffffffu, pl0, 2);
            pr0 += __shfl_xor_sync(0xffffffffu, pr0, 1); pr0 += __shfl_xor_sync(0xffffffffu, pr0, 2);
            pl1 += __shfl_xor_sync(0xffffffffu, pl1, 1); pl1 += __shfl_xor_sync(0xffffffffu, pl1, 2);
            pr1 += __shfl_xor_sync(0xffffffffu, pr1, 1); pr1 += __shfl_xor_sync(0xffffffffu, pr1, 2);
            if (t4 == 0) {
                int h = wn*4 + hh;
                if (r0 < NN) {
                    g_el[(m*NN + r0)*NH + h] = pl0;
                    g_er[(m*NN + r0)*NH + h] = pr0;
                }
                if (r0 + 8 < NN) {
                    g_el[(m*NN + r0 + 8)*NH + h] = pl1;
                    g_er[(m*NN + r0 + 8)*NH + h] = pr1;
                }
            }
        }
    }
}

// ---- SA GEMM tf32 + fused tanh epilogue ----
__global__ __launch_bounds__(256, 2) void k_sa_mma(const float* __restrict__ B1,
                                                   const float* __restrict__ W2) {
    __shared__ __align__(16) float sA[128*FSTR], sB[128*FSTR];
    __shared__ float s_b1[128], s_w2[128];
    int tid = threadIdx.x, w = tid >> 5, lane = tid & 31;
    int g = lane >> 2, t4 = lane & 3;
    int row0 = blockIdx.x * 128;
    if (tid < 128) { s_b1[tid] = B1[tid]; s_w2[tid] = W2[tid]; }
    uint32_t aA = smem_u32(sA), aB = smem_u32(sB);
    float acc[16][4];
#pragma unroll
    for (int j = 0; j < 16; j++)
#pragma unroll
        for (int i = 0; i < 4; i++) acc[j][i] = 0.f;

    for (int kc = 0; kc < 4; kc++) {
        int k0 = kc * 32;
#pragma unroll
        for (int i = 0; i < 4; i++) {
            int p = i * 256 + tid;
            int r = p >> 3, q = p & 7;
            int row = row0 + r;
            const float* src = g_z + (size_t)(row < SAROWS ? row : 0) * HDIM + k0 + q * 4;
            cp_async16z(aA + (uint32_t)(r*FSTR + q*4)*4, src, row < SAROWS ? 16 : 0);
            cp_async16(aB + (uint32_t)(r*FSTR + q*4)*4, g_w1t + (size_t)r * HDIM + k0 + q * 4);
        }
        CP_COMMIT();
        CP_WAIT0();
        __syncthreads();
#pragma unroll
        for (int ks = 0; ks < 4; ks++) {
            int kb = ks * 8;
            int ar_ = w*16 + g;
            uint32_t af[4];
            af[0] = tf32r_u(sA[ar_*FSTR + kb + t4]);
            af[1] = tf32r_u(sA[(ar_+8)*FSTR + kb + t4]);
            af[2] = tf32r_u(sA[ar_*FSTR + kb + t4 + 4]);
            af[3] = tf32r_u(sA[(ar_+8)*FSTR + kb + t4 + 4]);
#pragma unroll
            for (int jp = 0; jp < 16; jp++) {
                int bn = jp*8 + g;
                uint32_t b0 = __float_as_uint(sB[bn*FSTR + kb + t4]);
                uint32_t b1 = __float_as_uint(sB[bn*FSTR + kb + t4 + 4]);
                mma_tf32(acc[jp], af, b0, b1);
            }
        }
        __syncthreads();
    }
    float s0 = 0.f, s1 = 0.f;
#pragma unroll
    for (int j = 0; j < 16; j++) {
        int col = j * 8 + t4 * 2;
        float b0 = s_b1[col], b1v = s_b1[col + 1];
        float w0 = s_w2[col], w1v = s_w2[col + 1];
        s0 += tanhf(acc[j][0] + b0) * w0 + tanhf(acc[j][1] + b1v) * w1v;
        s1 += tanhf(acc[j][2] + b0) * w0 + tanhf(acc[j][3] + b1v) * w1v;
    }
    s0 += __shfl_xor_sync(0xffffffffu, s0, 1); s0 += __shfl_xor_sync(0xffffffffu, s0, 2);
    s1 += __shfl_xor_sync(0xffffffffu, s1, 1); s1 += __shfl_xor_sync(0xffffffffu, s1, 2);
    if (t4 == 0) {
        int r0 = row0 + w * 16 + g;
        if (r0 < SAROWS)     g_w[r0]     = s0;
        if (r0 + 8 < SAROWS) g_w[r0 + 8] = s1;
    }
}

__global__ void k_hist(const int* __restrict__ edges) {
    int idx = blockIdx.x * blockDim.x + threadIdx.x;
    if (idx >= MM*EE) return;
    int m = idx / EE, e = idx - m*EE;
    atomicAdd(&g_deg[m*NN + edges[(size_t)m*2*EE + EE + e]], 1);
}

__global__ void k_scan() {
    __shared__ int sh[1024];
    int m = blockIdx.x, t = threadIdx.x;
    const int CH = (NN + 1023) / 1024;
    int base = t * CH, sum = 0;
    for (int i = 0; i < CH; i++) { int idx = base+i; if (idx < NN) sum += g_deg[m*NN+idx]; }
    sh[t] = sum; __syncthreads();
    for (int d = 1; d < 1024; d <<= 1) {
        int v = (t >= d) ? sh[t-d] : 0; __syncthreads();
        sh[t] += v; __syncthreads();
    }
    int run = sh[t] - sum;
    for (int i = 0; i < CH; i++) {
        int idx = base+i;
        if (idx < NN) { g_off[m*(NN+1)+idx] = run; g_cur[m*NN+idx] = run; run += g_deg[m*NN+idx]; }
    }
    if (t == 1023) g_off[m*(NN+1)+NN] = sh[1023];
}

__global__ void k_scatter(const int* __restrict__ edges) {
    int idx = blockIdx.x * blockDim.x + threadIdx.x;
    if (idx >= MM*EE) return;
    int m = idx / EE, e = idx - m*EE;
    int src = edges[(size_t)m*2*EE + e];
    int dst = edges[(size_t)m*2*EE + EE + e];
    g_srt[(size_t)m*EE + atomicAdd(&g_cur[m*NN + dst], 1)] = src;
}

// ---- GAT aggregation: warp/dst, bf16 gather, unroll-4 (MLP x4) ----
__global__ __launch_bounds__(256) void k_agg() {
    int lane = threadIdx.x & 31;
    int wid  = (blockIdx.x * blockDim.x + threadIdx.x) >> 5;
    int m    = blockIdx.y;
    if (wid >= NN) return;
    int n = wid, h = lane >> 2;
    int beg = g_off[m*(NN+1)+n], end = g_off[m*(NN+1)+n+1];
    float ern = g_er[(m*NN+n)*NH + h];
    const __nv_bfloat16* featm = g_feat16 + (size_t)m*HDIM*NN;
    const float* elm = g_el + m*NN*NH;
    const int*   srcs = g_srt + (size_t)m*EE;
    float den = 0.f, ax = 0.f, ay = 0.f, az = 0.f, aw = 0.f;
    float dn2 = 0.f, bx = 0.f, by = 0.f, bz = 0.f, bw = 0.f;
    int i = beg;
    for (; i + 4 <= end; i += 4) {
        int s0 = __ldg(srcs + i),     s1 = __ldg(srcs + i + 1);
        int s2 = __ldg(srcs + i + 2), s3 = __ldg(srcs + i + 3);
        float e0 = __ldg(elm + s0*NH + h), e1 = __ldg(elm + s1*NH + h);
        float e2 = __ldg(elm + s2*NH + h), e3 = __ldg(elm + s3*NH + h);
        uint2 f0 = *(const uint2*)(featm + (size_t)s0*HDIM + lane*4);
        uint2 f1 = *(const uint2*)(featm + (size_t)s1*HDIM + lane*4);
        uint2 f2 = *(const uint2*)(featm + (size_t)s2*HDIM + lane*4);
        uint2 f3 = *(const uint2*)(featm + (size_t)s3*HDIM + lane*4);
        e0 += ern; e1 += ern; e2 += ern; e3 += ern;
        e0 = (e0 > 0.f) ? e0 : 0.2f*e0;
        e1 = (e1 > 0.f) ? e1 : 0.2f*e1;
        e2 = (e2 > 0.f) ? e2 : 0.2f*e2;
        e3 = (e3 > 0.f) ? e3 : 0.2f*e3;
        float x0 = __expf(e0), x1 = __expf(e1), x2 = __expf(e2), x3 = __expf(e3);
        den += x0 + x2; dn2 += x1 + x3;
        float2 u0 = __bfloat1622float2(*(__nv_bfloat162*)&f0.x);
        float2 u1 = __bfloat1622float2(*(__nv_bfloat162*)&f0.y);
        float2 v0 = __bfloat1622float2(*(__nv_bfloat162*)&f1.x);
        float2 v1 = __bfloat1622float2(*(__nv_bfloat162*)&f1.y);
        float2 p0 = __bfloat1622float2(*(__nv_bfloat162*)&f2.x);
        float2 p1 = __bfloat1622float2(*(__nv_bfloat162*)&f2.y);
        float2 q0 = __bfloat1622float2(*(__nv_bfloat162*)&f3.x);
        float2 q1 = __bfloat1622float2(*(__nv_bfloat162*)&f3.y);
        ax += x0*u0.x + x2*p0.x; ay += x0*u0.y + x2*p0.y;
        az += x0*u1.x + x2*p1.x; aw += x0*u1.y + x2*p1.y;
        bx += x1*v0.x + x3*q0.x; by += x1*v0.y + x3*q0.y;
        bz += x1*v1.x + x3*q1.x; bw += x1*v1.y + x3*q1.y;
    }
    for (; i < end; i++) {
        int s0 = __ldg(srcs + i);
        float e0 = __ldg(elm + s0*NH + h) + ern;
        uint2 f0 = *(const uint2*)(featm + (size_t)s0*HDIM + lane*4);
        e0 = (e0 > 0.f) ? e0 : 0.2f*e0;
        float x0 = __expf(e0);
        den += x0;
        float2 u0 = __bfloat1622float2(*(__nv_bfloat162*)&f0.x);
        float2 u1 = __bfloat1622float2(*(__nv_bfloat162*)&f0.y);
        ax += x0*u0.x; ay += x0*u0.y; az += x0*u1.x; aw += x0*u1.y;
    }
    den += dn2; ax += bx; ay += by; az += bz; aw += bw;
    float inv = (end > beg) ? 1.f/den : 0.f;
    float4 o; float v;
    v = ax*inv; o.x = (v > 0.f) ? v : expm1f(v);
    v = ay*inv; o.y = (v > 0.f) ? v : expm1f(v);
    v = az*inv; o.z = (v > 0.f) ? v : expm1f(v);
    v = aw*inv; o.w = (v > 0.f) ? v : expm1f(v);
    *(float4*)(g_z + (size_t)(n*MM + m)*HDIM + lane*4) = o;
}

__global__ void k_wmax() {
    float lm0 = -INFINITY, lm1 = -INFINITY, lm2 = -INFINITY;
    for (int n = blockIdx.x*blockDim.x + threadIdx.x; n < NN; n += gridDim.x*blockDim.x) {
        lm0 = fmaxf(lm0, g_w[n*3+0]); lm1 = fmaxf(lm1, g_w[n*3+1]); lm2 = fmaxf(lm2, g_w[n*3+2]);
    }
#pragma unroll
    for (int off = 16; off > 0; off >>= 1) {
        lm0 = fmaxf(lm0, __shfl_down_sync(0xffffffffu, lm0, off));
        lm1 = fmaxf(lm1, __shfl_down_sync(0xffffffffu, lm1, off));
        lm2 = fmaxf(lm2, __shfl_down_sync(0xffffffffu, lm2, off));
    }
    if ((threadIdx.x & 31) == 0) {
        atomicMaxF(&g_wmax[0], lm0); atomicMaxF(&g_wmax[1], lm1); atomicMaxF(&g_wmax[2], lm2);
    }
}

__global__ void k_sden() {
    float w0 = g_wmax[0], w1 = g_wmax[1], w2 = g_wmax[2];
    float d0 = 0.f, d1 = 0.f, d2 = 0.f;
    for (int n = blockIdx.x*blockDim.x + threadIdx.x; n < NN; n += gridDim.x*blockDim.x) {
        float s0 = __expf(g_w[n*3+0]-w0), s1 = __expf(g_w[n*3+1]-w1), s2 = __expf(g_w[n*3+2]-w2);
        g_s[n*3+0] = s0; g_s[n*3+1] = s1; g_s[n*3+2] = s2;
        d0 += s0; d1 += s1; d2 += s2;
    }
#pragma unroll
    for (int off = 16; off > 0; off >>= 1) {
        d0 += __shfl_down_sync(0xffffffffu, d0, off);
        d1 += __shfl_down_sync(0xffffffffu, d1, off);
        d2 += __shfl_down_sync(0xffffffffu, d2, off);
    }
    if ((threadIdx.x & 31) == 0) {
        atomicAdd(&g_den[0], d0); atomicAdd(&g_den[1], d1); atomicAdd(&g_den[2], d2);
    }
}

__global__ __launch_bounds__(384) void k_fused() {
    int t = threadIdx.x, ms = t >> 7;
    float acc = 0.f;
    for (int n = blockIdx.x; n < NN; n += gridDim.x)
        acc += g_s[n*3 + ms] * g_z[(size_t)n*ZROW + t];
    atomicAdd(&g_fus[t], acc);
}

__global__ void k_final(const float* __restrict__ PW, const float* __restrict__ PB,
                        float* __restrict__ out) {
    int t = threadIdx.x;
    if (t >= MM*OUTC) return;
    int m = t / OUTC, o = t - m*OUTC;
    float a = 0.f;
#pragma unroll 8
    for (int c = 0; c < HDIM; c++) a += g_fus[m*HDIM + c] * __ldg(PW + c*OUTC + o);
    out[t] = a / g_den[m] + __ldg(PB + o);
}

extern "C" void kernel_launch(void* const* d_in, const int* in_sizes, int n_in,
                              void* d_out, int out_size) {
    const float* h      = (const float*)d_in[0];
    const int*   edges  = (const int*)d_in[1];
    const float* fc_w   = (const float*)d_in[2];
    const float* attn_l = (const float*)d_in[3];
    const float* attn_r = (const float*)d_in[4];
    const float* sa_w1  = (const float*)d_in[5];
    const float* sa_b1  = (const float*)d_in[6];
    const float* sa_w2  = (const float*)d_in[7];
    const float* pred_w = (const float*)d_in[8];
    const float* pred_b = (const float*)d_in[9];
    float* out = (float*)d_out;

    static int inited = 0;
    static cudaStream_t s2;
    static cudaEvent_t ev_fork, ev_join;
    if (!inited) {
        cudaFuncSetAttribute(k_feat_mma, cudaFuncAttributeMaxDynamicSharedMemorySize, FEAT_DYN);
        cudaStreamCreateWithFlags(&s2, cudaStreamNonBlocking);
        cudaEventCreateWithFlags(&ev_fork, cudaEventDisableTiming);
        cudaEventCreateWithFlags(&ev_join, cudaEventDisableTiming);
        inited = 1;
    }

    // fork: CSR build (init->hist->scan->scatter) on s2, GEMM prep+feat on main
    cudaEventRecord(ev_fork, 0);
    cudaStreamWaitEvent(s2, ev_fork, 0);
    k_init<<<(MM*NN + 255)/256, 256, 0, s2>>>();
    k_hist<<<(MM*EE + 255)/256, 256, 0, s2>>>(edges);
    k_scan<<<MM, 1024, 0, s2>>>();
    k_scatter<<<(MM*EE + 255)/256, 256, 0, s2>>>(edges);
    cudaEventRecord(ev_join, s2);

    k_prep<<<(MM*HDIM*INSZ + SAH*HDIM + 255)/256, 256>>>(fc_w, sa_w1);
    k_feat_mma<<<dim3((NN + 127)/128, MM), 256, FEAT_DYN>>>(h, attn_l, attn_r);

    cudaStreamWaitEvent(0, ev_join, 0);
    k_agg<<<dim3((NN + 7)/8, MM), 256>>>();
    k_sa_mma<<<(SAROWS + 127)/128, 256>>>(sa_b1, sa_w2);
    k_wmax<<<64, 256>>>();
    k_sden<<<196, 256>>>();
    k_fused<<<256, 384>>>();
    k_final<<<1, 32>>>(pred_w, pred_b, out);
}

// round 11
// speedup vs baseline: 2.0630x; 1.0519x over previous
#include <cuda_runtime.h>
#include <cuda_bf16.h>
#include <math.h>
#include <stdint.h>

#define NN   50000
#define EE   800000
#define MM   3
#define INSZ 256
#define HDIM 128
#define NH   8
#define DH   16
#define OUTC 8
#define SAH  128
#define ZROW (MM*HDIM)
#define SAROWS (NN*MM)
#define FSTR 36
#define FEAT_DYN (4*128*FSTR*4)

__device__ __align__(16) __nv_bfloat16 g_feat16[(size_t)MM*NN*HDIM];
__device__ __align__(16) float g_z[(size_t)SAROWS*HDIM];
__device__ float g_el[MM*NN*NH];
__device__ float g_er[MM*NN*NH];
__device__ int   g_deg[MM*NN];
__device__ int   g_off[MM*(NN+1)];
__device__ int   g_cur[MM*NN];
__device__ int   g_srt[MM*EE];
__device__ float g_w[SAROWS];
__device__ float g_wmax[MM];
__device__ float g_den[MM];
__device__ float g_fus[MM*HDIM];
__device__ __align__(16) float g_wt[MM*HDIM*INSZ];
__device__ __align__(16) float g_w1t[SAH*HDIM];

__device__ __forceinline__ uint32_t smem_u32(const void* p) {
    uint32_t a;
    asm("{ .reg .u64 t; cvta.to.shared.u64 t, %1; cvt.u32.u64 %0, t; }" : "=r"(a) : "l"(p));
    return a;
}
__device__ __forceinline__ void cp_async16(uint32_t saddr, const void* g) {
    asm volatile("cp.async.cg.shared.global [%0], [%1], 16;" :: "r"(saddr), "l"(g));
}
__device__ __forceinline__ void cp_async16z(uint32_t saddr, const void* g, int sz) {
    asm volatile("cp.async.cg.shared.global [%0], [%1], 16, %2;" :: "r"(saddr), "l"(g), "r"(sz));
}
#define CP_COMMIT() asm volatile("cp.async.commit_group;" ::: "memory")
#define CP_WAIT0()  asm volatile("cp.async.wait_group 0;" ::: "memory")
#define CP_WAIT1()  asm volatile("cp.async.wait_group 1;" ::: "memory")
__device__ __forceinline__ uint32_t tf32r_u(float x) {
    uint32_t u;
    asm("cvt.rna.tf32.f32 %0, %1;" : "=r"(u) : "f"(x));
    return u;
}
__device__ __forceinline__ void mma_tf32(float* c, const uint32_t* a, uint32_t b0, uint32_t b1) {
    asm volatile("mma.sync.aligned.m16n8k8.row.col.f32.tf32.tf32.f32 "
        "{%0,%1,%2,%3}, {%4,%5,%6,%7}, {%8,%9}, {%0,%1,%2,%3};"
        : "+f"(c[0]), "+f"(c[1]), "+f"(c[2]), "+f"(c[3])
        : "r"(a[0]), "r"(a[1]), "r"(a[2]), "r"(a[3]), "r"(b0), "r"(b1));
}
__device__ __forceinline__ void atomicMaxF(float* addr, float v) {
    if (v >= 0.f) atomicMax((int*)addr, __float_as_int(v));
    else          atomicMin((unsigned int*)addr, __float_as_uint(v));
}

__global__ void k_init() {
    int idx = blockIdx.x * blockDim.x + threadIdx.x;
    if (idx < MM*NN) g_deg[idx] = 0;
    if (idx < MM*HDIM) g_fus[idx] = 0.f;
    if (idx < MM) { g_den[idx] = 0.f; g_wmax[idx] = -INFINITY; }
}

__global__ void k_prep(const float* __restrict__ fc_w, const float* __restrict__ sa_w1) {
    int idx = blockIdx.x * blockDim.x + threadIdx.x;
    if (idx < MM*HDIM*INSZ) {
        int m = idx / (HDIM*INSZ), r = idx - m*(HDIM*INSZ);
        int n = r / INSZ, k = r - n*INSZ;
        g_wt[idx] = __uint_as_float(tf32r_u(fc_w[((size_t)m*INSZ + k)*HDIM + n]));
    } else {
        int j = idx - MM*HDIM*INSZ;
        if (j < SAH*HDIM) {
            int n = j / HDIM, k = j - n*HDIM;
            g_w1t[j] = __uint_as_float(tf32r_u(sa_w1[(size_t)k*SAH + n]));
        }
    }
}

// ---- feat = h @ fc_w[m], tf32 mma, double-buffered cp.async pipeline ----
__global__ __launch_bounds__(256, 2) void k_feat_mma(const float* __restrict__ A,
                                                     const float* __restrict__ AL,
                                                     const float* __restrict__ AR) {
    extern __shared__ __align__(16) float smf[];
    float* sA = smf;
    float* sB = smf + 2*128*FSTR;
    __shared__ float s_al[128], s_ar[128];
    int tid = threadIdx.x, w = tid >> 5, lane = tid & 31;
    int wm = w >> 1, wn = w & 1, g = lane >> 2, t4 = lane & 3;
    int m = blockIdx.y, row0 = blockIdx.x * 128;
    if (tid < 128) { s_al[tid] = AL[m*HDIM + tid]; s_ar[tid] = AR[m*HDIM + tid]; }
    float acc[2][8][4];
#pragma unroll
    for (int mt = 0; mt < 2; mt++)
#pragma unroll
        for (int j = 0; j < 8; j++)
#pragma unroll
            for (int i = 0; i < 4; i++) acc[mt][j][i] = 0.f;

    const float* Bm = g_wt + (size_t)m * HDIM * INSZ;
    int r_ld = tid >> 3, q_ld = tid & 7;

    auto stage = [&](int kc, int buf) {
        int k0 = kc * 32;
        uint32_t aA = smem_u32(sA + buf*128*FSTR);
        uint32_t aB = smem_u32(sB + buf*128*FSTR);
#pragma unroll
        for (int i = 0; i < 4; i++) {
            int r = r_ld + i*32, q = q_ld;
            int node = row0 + r;
            const float* src = A + (size_t)(node < NN ? node : 0) * INSZ + k0 + q * 4;
            cp_async16z(aA + (uint32_t)(r*FSTR + q*4)*4, src, node < NN ? 16 : 0);
            cp_async16(aB + (uint32_t)(r*FSTR + q*4)*4, Bm + (size_t)r * INSZ + k0 + q * 4);
        }
        CP_COMMIT();
    };

    stage(0, 0);
    for (int kc = 0; kc < 8; kc++) {
        if (kc < 7) { stage(kc + 1, (kc + 1) & 1); CP_WAIT1(); }
        else        { CP_WAIT0(); }
        __syncthreads();
        const float* sAb = sA + (kc & 1)*128*FSTR;
        const float* sBb = sB + (kc & 1)*128*FSTR;
#pragma unroll
        for (int ks = 0; ks < 4; ks++) {
            int kb = ks * 8;
            uint32_t af[2][4];
#pragma unroll
            for (int mt = 0; mt < 2; mt++) {
                int ar_ = wm*32 + mt*16 + g;
                af[mt][0] = tf32r_u(sAb[ar_*FSTR + kb + t4]);
                af[mt][1] = tf32r_u(sAb[(ar_+8)*FSTR + kb + t4]);
                af[mt][2] = tf32r_u(sAb[ar_*FSTR + kb + t4 + 4]);
                af[mt][3] = tf32r_u(sAb[(ar_+8)*FSTR + kb + t4 + 4]);
            }
#pragma unroll
            for (int jp = 0; jp < 8; jp++) {
                int bn = wn*64 + jp*8 + g;
                uint32_t b0 = __float_as_uint(sBb[bn*FSTR + kb + t4]);
                uint32_t b1 = __float_as_uint(sBb[bn*FSTR + kb + t4 + 4]);
                mma_tf32(acc[0][jp], af[0], b0, b1);
                mma_tf32(acc[1][jp], af[1], b0, b1);
            }
        }
        __syncthreads();
    }
    __nv_bfloat16* outp = g_feat16 + (size_t)m * NN * HDIM;
#pragma unroll
    for (int mt = 0; mt < 2; mt++) {
        int r0 = row0 + wm*32 + mt*16 + g;
#pragma unroll
        for (int jp = 0; jp < 8; jp++) {
            int col = wn*64 + jp*8 + t4*2;
            if (r0 < NN)
                *(__nv_bfloat162*)(outp + (size_t)r0 * HDIM + col) =
                    __float22bfloat162_rn(make_float2(acc[mt][jp][0], acc[mt][jp][1]));
            if (r0 + 8 < NN)
                *(__nv_bfloat162*)(outp + (size_t)(r0 + 8) * HDIM + col) =
                    __float22bfloat162_rn(make_float2(acc[mt][jp][2], acc[mt][jp][3]));
        }
#pragma unroll
        for (int hh = 0; hh < 4; hh++) {
            float pl0 = 0.f, pr0 = 0.f, pl1 = 0.f, pr1 = 0.f;
#pragma unroll
            for (int jj = 2*hh; jj <= 2*hh+1; jj++) {
                int c0 = wn*64 + jj*8 + t4*2, c1 = c0 + 1;
                float a0 = s_al[c0], a1 = s_al[c1], b0 = s_ar[c0], b1 = s_ar[c1];
                pl0 += acc[mt][jj][0]*a0 + acc[mt][jj][1]*a1;
                pr0 += acc[mt][jj][0]*b0 + acc[mt][jj][1]*b1;
                pl1 += acc[mt][jj][2]*a0 + acc[mt][jj][3]*a1;
                pr1 += acc[mt][jj][2]*b0 + acc[mt][jj][3]*b1;
            }
            pl0 += __shfl_xor_sync(0xffffffffu, pl0, 1); pl0 += __shfl_xor_sync(0xffffffffu, pl0, 2);
            pr0 += __shfl_xor_sync(0xffffffffu, pr0, 1); pr0 += __shfl_xor_sync(0xffffffffu, pr0, 2);
            pl1 += __shfl_xor_sync(0xffffffffu, pl1, 1); pl1 += __shfl_xor_sync(0xffffffffu, pl1, 2);
            pr1 += __shfl_xor_sync(0xffffffffu, pr1, 1); pr1 += __shfl_xor_sync(0xffffffffu, pr1, 2);
            if (t4 == 0) {
                int h = wn*4 + hh;
                if (r0 < NN) {
                    g_el[(m*NN + r0)*NH + h] = pl0;
                    g_er[(m*NN + r0)*NH + h] = pr0;
                }
                if (r0 + 8 < NN) {
                    g_el[(m*NN + r0 + 8)*NH + h] = pl1;
                    g_er[(m*NN + r0 + 8)*NH + h] = pr1;
                }
            }
        }
    }
}

// ---- SA GEMM tf32 + fused tanh epilogue + fused wmax ----
__global__ __launch_bounds__(256, 2) void k_sa_mma(const float* __restrict__ B1,
                                                   const float* __restrict__ W2) {
    __shared__ __align__(16) float sA[128*FSTR], sB[128*FSTR];
    __shared__ float s_b1[128], s_w2[128];
    __shared__ float bmax[MM];
    int tid = threadIdx.x, w = tid >> 5, lane = tid & 31;
    int g = lane >> 2, t4 = lane & 3;
    int row0 = blockIdx.x * 128;
    if (tid < 128) { s_b1[tid] = B1[tid]; s_w2[tid] = W2[tid]; }
    if (tid < MM) bmax[tid] = -INFINITY;
    uint32_t aA = smem_u32(sA), aB = smem_u32(sB);
    float acc[16][4];
#pragma unroll
    for (int j = 0; j < 16; j++)
#pragma unroll
        for (int i = 0; i < 4; i++) acc[j][i] = 0.f;

    for (int kc = 0; kc < 4; kc++) {
        int k0 = kc * 32;
#pragma unroll
        for (int i = 0; i < 4; i++) {
            int p = i * 256 + tid;
            int r = p >> 3, q = p & 7;
            int row = row0 + r;
            const float* src = g_z + (size_t)(row < SAROWS ? row : 0) * HDIM + k0 + q * 4;
            cp_async16z(aA + (uint32_t)(r*FSTR + q*4)*4, src, row < SAROWS ? 16 : 0);
            cp_async16(aB + (uint32_t)(r*FSTR + q*4)*4, g_w1t + (size_t)r * HDIM + k0 + q * 4);
        }
        CP_COMMIT();
        CP_WAIT0();
        __syncthreads();
#pragma unroll
        for (int ks = 0; ks < 4; ks++) {
            int kb = ks * 8;
            int ar_ = w*16 + g;
            uint32_t af[4];
            af[0] = tf32r_u(sA[ar_*FSTR + kb + t4]);
            af[1] = tf32r_u(sA[(ar_+8)*FSTR + kb + t4]);
            af[2] = tf32r_u(sA[ar_*FSTR + kb + t4 + 4]);
            af[3] = tf32r_u(sA[(ar_+8)*FSTR + kb + t4 + 4]);
#pragma unroll
            for (int jp = 0; jp < 16; jp++) {
                int bn = jp*8 + g;
                uint32_t b0 = __float_as_uint(sB[bn*FSTR + kb + t4]);
                uint32_t b1 = __float_as_uint(sB[bn*FSTR + kb + t4 + 4]);
                mma_tf32(acc[jp], af, b0, b1);
            }
        }
        __syncthreads();
    }
    float s0 = 0.f, s1 = 0.f;
#pragma unroll
    for (int j = 0; j < 16; j++) {
        int col = j * 8 + t4 * 2;
        float b0 = s_b1[col], b1v = s_b1[col + 1];
        float w0 = s_w2[col], w1v = s_w2[col + 1];
        s0 += tanhf(acc[j][0] + b0) * w0 + tanhf(acc[j][1] + b1v) * w1v;
        s1 += tanhf(acc[j][2] + b0) * w0 + tanhf(acc[j][3] + b1v) * w1v;
    }
    s0 += __shfl_xor_sync(0xffffffffu, s0, 1); s0 += __shfl_xor_sync(0xffffffffu, s0, 2);
    s1 += __shfl_xor_sync(0xffffffffu, s1, 1); s1 += __shfl_xor_sync(0xffffffffu, s1, 2);
    if (t4 == 0) {
        int r0 = row0 + w * 16 + g;
        if (r0 < SAROWS)     { g_w[r0]     = s0; atomicMaxF(&bmax[r0 % 3], s0); }
        if (r0 + 8 < SAROWS) { g_w[r0 + 8] = s1; atomicMaxF(&bmax[(r0 + 8) % 3], s1); }
    }
    __syncthreads();
    if (tid < MM) atomicMaxF(&g_wmax[tid], bmax[tid]);
}

__global__ void k_hist(const int* __restrict__ edges) {
    int idx = blockIdx.x * blockDim.x + threadIdx.x;
    if (idx >= MM*EE) return;
    int m = idx / EE, e = idx - m*EE;
    atomicAdd(&g_deg[m*NN + edges[(size_t)m*2*EE + EE + e]], 1);
}

__global__ void k_scan() {
    __shared__ int sh[1024];
    int m = blockIdx.x, t = threadIdx.x;
    const int CH = (NN + 1023) / 1024;
    int base = t * CH, sum = 0;
    for (int i = 0; i < CH; i++) { int idx = base+i; if (idx < NN) sum += g_deg[m*NN+idx]; }
    sh[t] = sum; __syncthreads();
    for (int d = 1; d < 1024; d <<= 1) {
        int v = (t >= d) ? sh[t-d] : 0; __syncthreads();
        sh[t] += v; __syncthreads();
    }
    int run = sh[t] - sum;
    for (int i = 0; i < CH; i++) {
        int idx = base+i;
        if (idx < NN) { g_off[m*(NN+1)+idx] = run; g_cur[m*NN+idx] = run; run += g_deg[m*NN+idx]; }
    }
    if (t == 1023) g_off[m*(NN+1)+NN] = sh[1023];
}

__global__ void k_scatter(const int* __restrict__ edges) {
    int idx = blockIdx.x * blockDim.x + threadIdx.x;
    if (idx >= MM*EE) return;
    int m = idx / EE, e = idx - m*EE;
    int src = edges[(size_t)m*2*EE + e];
    int dst = edges[(size_t)m*2*EE + EE + e];
    g_srt[(size_t)m*EE + atomicAdd(&g_cur[m*NN + dst], 1)] = src;
}

// ---- GAT aggregation: warp/dst, bf16 gather, unroll-8 (MLP x8) ----
__global__ __launch_bounds__(256) void k_agg() {
    int lane = threadIdx.x & 31;
    int wid  = (blockIdx.x * blockDim.x + threadIdx.x) >> 5;
    int m    = blockIdx.y;
    if (wid >= NN) return;
    int n = wid, h = lane >> 2;
    int beg = g_off[m*(NN+1)+n], end = g_off[m*(NN+1)+n+1];
    float ern = g_er[(m*NN+n)*NH + h];
    const __nv_bfloat16* featm = g_feat16 + (size_t)m*HDIM*NN;
    const float* elm = g_el + m*NN*NH;
    const int*   srcs = g_srt + (size_t)m*EE;
    float den = 0.f, ax = 0.f, ay = 0.f, az = 0.f, aw = 0.f;
    float dn2 = 0.f, bx = 0.f, by = 0.f, bz = 0.f, bw = 0.f;
    int i = beg;
    for (; i + 8 <= end; i += 8) {
        int s[8]; float e[8]; uint2 f[8];
#pragma unroll
        for (int j = 0; j < 8; j++) s[j] = __ldg(srcs + i + j);
#pragma unroll
        for (int j = 0; j < 8; j++) e[j] = __ldg(elm + s[j]*NH + h);
#pragma unroll
        for (int j = 0; j < 8; j++) f[j] = *(const uint2*)(featm + (size_t)s[j]*HDIM + lane*4);
#pragma unroll
        for (int j = 0; j < 8; j++) {
            float ev = e[j] + ern;
            ev = (ev > 0.f) ? ev : 0.2f*ev;
            float x = __expf(ev);
            float2 u0 = __bfloat1622float2(*(__nv_bfloat162*)&f[j].x);
            float2 u1 = __bfloat1622float2(*(__nv_bfloat162*)&f[j].y);
            if (j & 1) { dn2 += x; bx += x*u0.x; by += x*u0.y; bz += x*u1.x; bw += x*u1.y; }
            else       { den += x; ax += x*u0.x; ay += x*u0.y; az += x*u1.x; aw += x*u1.y; }
        }
    }
    for (; i + 2 <= end; i += 2) {
        int s0 = __ldg(srcs + i), s1 = __ldg(srcs + i + 1);
        float e0 = __ldg(elm + s0*NH + h) + ern;
        float e1 = __ldg(elm + s1*NH + h) + ern;
        uint2 f0 = *(const uint2*)(featm + (size_t)s0*HDIM + lane*4);
        uint2 f1 = *(const uint2*)(featm + (size_t)s1*HDIM + lane*4);
        e0 = (e0 > 0.f) ? e0 : 0.2f*e0;
        e1 = (e1 > 0.f) ? e1 : 0.2f*e1;
        float x0 = __expf(e0), x1 = __expf(e1);
        den += x0; dn2 += x1;
        float2 u0 = __bfloat1622float2(*(__nv_bfloat162*)&f0.x);
        float2 u1 = __bfloat1622float2(*(__nv_bfloat162*)&f0.y);
        float2 v0 = __bfloat1622float2(*(__nv_bfloat162*)&f1.x);
        float2 v1 = __bfloat1622float2(*(__nv_bfloat162*)&f1.y);
        ax += x0*u0.x; ay += x0*u0.y; az += x0*u1.x; aw += x0*u1.y;
        bx += x1*v0.x; by += x1*v0.y; bz += x1*v1.x; bw += x1*v1.y;
    }
    if (i < end) {
        int s0 = __ldg(srcs + i);
        float e0 = __ldg(elm + s0*NH + h) + ern;
        uint2 f0 = *(const uint2*)(featm + (size_t)s0*HDIM + lane*4);
        e0 = (e0 > 0.f) ? e0 : 0.2f*e0;
        float x0 = __expf(e0);
        den += x0;
        float2 u0 = __bfloat1622float2(*(__nv_bfloat162*)&f0.x);
        float2 u1 = __bfloat1622float2(*(__nv_bfloat162*)&f0.y);
        ax += x0*u0.x; ay += x0*u0.y; az += x0*u1.x; aw += x0*u1.y;
    }
    den += dn2; ax += bx; ay += by; az += bz; aw += bw;
    float inv = (end > beg) ? 1.f/den : 0.f;
    float4 o; float v;
    v = ax*inv; o.x = (v > 0.f) ? v : expm1f(v);
    v = ay*inv; o.y = (v > 0.f) ? v : expm1f(v);
    v = az*inv; o.z = (v > 0.f) ? v : expm1f(v);
    v = aw*inv; o.w = (v > 0.f) ? v : expm1f(v);
    *(float4*)(g_z + (size_t)(n*MM + m)*HDIM + lane*4) = o;
}

// ---- tail: s = exp(w - wmax); fus += s*z; den += s (fuses sden+fused) ----
__global__ __launch_bounds__(384) void k_tail() {
    int t = threadIdx.x, ms = t >> 7;
    float wm = g_wmax[ms];
    float acc = 0.f, dloc = 0.f;
    for (int n = blockIdx.x; n < NN; n += gridDim.x) {
        float s = __expf(g_w[n*3 + ms] - wm);
        acc += s * g_z[(size_t)n*ZROW + t];
        dloc += s;
    }
    atomicAdd(&g_fus[t], acc);
    if ((t & 127) == 0) atomicAdd(&g_den[ms], dloc);
}

__global__ void k_final(const float* __restrict__ PW, const float* __restrict__ PB,
                        float* __restrict__ out) {
    int t = threadIdx.x;
    if (t >= MM*OUTC) return;
    int m = t / OUTC, o = t - m*OUTC;
    float a = 0.f;
#pragma unroll 8
    for (int c = 0; c < HDIM; c++) a += g_fus[m*HDIM + c] * __ldg(PW + c*OUTC + o);
    out[t] = a / g_den[m] + __ldg(PB + o);
}

extern "C" void kernel_launch(void* const* d_in, const int* in_sizes, int n_in,
                              void* d_out, int out_size) {
    const float* h      = (const float*)d_in[0];
    const int*   edges  = (const int*)d_in[1];
    const float* fc_w   = (const float*)d_in[2];
    const float* attn_l = (const float*)d_in[3];
    const float* attn_r = (const float*)d_in[4];
    const float* sa_w1  = (const float*)d_in[5];
    const float* sa_b1  = (const float*)d_in[6];
    const float* sa_w2  = (const float*)d_in[7];
    const float* pred_w = (const float*)d_in[8];
    const float* pred_b = (const float*)d_in[9];
    float* out = (float*)d_out;

    static int inited = 0;
    static cudaStream_t s2;
    static cudaEvent_t ev_fork, ev_join;
    if (!inited) {
        cudaFuncSetAttribute(k_feat_mma, cudaFuncAttributeMaxDynamicSharedMemorySize, FEAT_DYN);
        cudaStreamCreateWithFlags(&s2, cudaStreamNonBlocking);
        cudaEventCreateWithFlags(&ev_fork, cudaEventDisableTiming);
        cudaEventCreateWithFlags(&ev_join, cudaEventDisableTiming);
        inited = 1;
    }

    cudaEventRecord(ev_fork, 0);
    cudaStreamWaitEvent(s2, ev_fork, 0);
    k_init<<<(MM*NN + 255)/256, 256, 0, s2>>>();
    k_hist<<<(MM*EE + 255)/256, 256, 0, s2>>>(edges);
    k_scan<<<MM, 1024, 0, s2>>>();
    k_scatter<<<(MM*EE + 255)/256, 256, 0, s2>>>(edges);
    cudaEventRecord(ev_join, s2);

    k_prep<<<(MM*HDIM*INSZ + SAH*HDIM + 255)/256, 256>>>(fc_w, sa_w1);
    k_feat_mma<<<dim3((NN + 127)/128, MM), 256, FEAT_DYN>>>(h, attn_l, attn_r);

    cudaStreamWaitEvent(0, ev_join, 0);
    k_agg<<<dim3((NN + 7)/8, MM), 256>>>();
    k_sa_mma<<<(SAROWS + 127)/128, 256>>>(sa_b1, sa_w2);
    k_tail<<<256, 384>>>();
    k_final<<<1, 32>>>(pred_w, pred_b, out);
}